// round 13
// baseline (speedup 1.0000x reference)
#include <cuda_runtime.h>
#include <cuda_fp16.h>
#include <cstdint>

// ---------------- problem constants ----------------
#define N_U      20000
#define N_O      10000
#define N_TOT    30000
#define CDIM     256
#define TXTD     1536
#define NCOLS    7
#define E_EDGES  10000
#define MAXP     16
#define NUM_NODES 30000
#define VOCAB    101

#define X_ROWS   210000
#define OFF_NODE 53760000
#define OFF_COL  53970000
#define OFF_TAB  54180000
#define OFF_F2P  54390000
#define OFF_NN   57750000

// ---------------- device scratch ----------------
__device__ int g_tbl[NUM_NODES * MAXP];
__device__ int g_cnt[N_O];
__device__ int g_slot[N_O * 32];
__device__ __half g_w_h[2 * CDIM * TXTD];   // W rounded to fp16

// ---------------- helpers ----------------
__device__ __forceinline__ uint32_t smem_u32(const void* p) {
    uint32_t a;
    asm("{ .reg .u64 t; cvta.to.shared.u64 t, %1; cvt.u32.u64 %0, t; }" : "=r"(a) : "l"(p));
    return a;
}

#define LDSM_X4(r0, r1, r2, r3, addr) \
    asm volatile("ldmatrix.sync.aligned.m8n8.x4.shared.b16 {%0,%1,%2,%3}, [%4];" \
        : "=r"(r0), "=r"(r1), "=r"(r2), "=r"(r3) : "r"(addr))

#define MMA16816H(d, a, b0, b1) \
    asm volatile("mma.sync.aligned.m16n8k16.row.col.f32.f16.f16.f32 " \
        "{%0,%1,%2,%3}, {%4,%5,%6,%7}, {%8,%9}, {%0,%1,%2,%3};" \
        : "+f"((d)[0]), "+f"((d)[1]), "+f"((d)[2]), "+f"((d)[3]) \
        : "r"((a)[0]), "r"((a)[1]), "r"((a)[2]), "r"((a)[3]), "r"(b0), "r"(b1))

__device__ __forceinline__ void cp16(uint32_t dst, const void* src, int pred_sz) {
    asm volatile("cp.async.cg.shared.global [%0], [%1], 16, %2;"
                 :: "r"(dst), "l"(src), "r"(pred_sz));
}
#define CP_COMMIT() asm volatile("cp.async.commit_group;" ::: "memory")
#define CP_WAIT1()  asm volatile("cp.async.wait_group 1;" ::: "memory")
#define CP_WAIT0()  asm volatile("cp.async.wait_group 0;" ::: "memory")

// ---------------- init scratch ----------------
__global__ void init_scratch_kernel() {
    int i = blockIdx.x * blockDim.x + threadIdx.x;
    if (i < NUM_NODES * MAXP) g_tbl[i] = -1;
    if (i < N_O) g_cnt[i] = 0;
}

// ---------------- W -> fp16 ----------------
__global__ void w_h_kernel(const float* __restrict__ uw, const float* __restrict__ ow) {
    int i = blockIdx.x * blockDim.x + threadIdx.x;
    if (i >= CDIM * TXTD) return;
    int idx = i * 2;
    float a, b;
    if (idx < CDIM * TXTD) { a = uw[idx]; b = uw[idx + 1]; }
    else { a = ow[idx - CDIM * TXTD]; b = ow[idx - CDIM * TXTD + 1]; }
    __half2 h = __floats2half2_rn(a, b);
    *(uint32_t*)&g_w_h[idx] = *reinterpret_cast<uint32_t*>(&h);
}

// ---------------- edges: scatter + per-child sort ----------------
__global__ void edge_scatter_kernel(const int* __restrict__ edge_index) {
    int i = blockIdx.x * blockDim.x + threadIdx.x;
    if (i >= E_EDGES) return;
    int c = edge_index[i];
    int s = atomicAdd(&g_cnt[c], 1);
    if (s < 32) g_slot[c * 32 + s] = i;
}

__global__ void edge_sort_write_kernel(const int* __restrict__ edge_index) {
    int c = blockIdx.x * blockDim.x + threadIdx.x;
    if (c >= N_O) return;
    int n = g_cnt[c];
    if (n > 32) n = 32;
    int idx[32];
    for (int j = 0; j < n; j++) {
        int v = g_slot[c * 32 + j];
        int pos = j;
        while (pos > 0 && idx[pos - 1] > v) { idx[pos] = idx[pos - 1]; pos--; }
        idx[pos] = v;
    }
    int lim = n < MAXP ? n : MAXP;
    for (int r = 0; r < lim; r++)
        g_tbl[(N_U + c) * MAXP + r] = edge_index[E_EDGES + idx[r]];
}

// ---------------- f2p gather ----------------
__global__ void f2p_gather_kernel(float* __restrict__ out) {
    int i = blockIdx.x * blockDim.x + threadIdx.x;
    if (i >= X_ROWS * MAXP) return;
    int row = i >> 4;
    int s = i & (MAXP - 1);
    int node;
    if (row < NCOLS * N_U) node = row % N_U;
    else                   node = N_U + (row - NCOLS * N_U) % N_O;
    out[OFF_F2P + i] = (float)g_tbl[node * MAXP + s];
}

// ---------------- index arrays + num_nodes ----------------
__global__ void index_kernel(float* __restrict__ out) {
    int i = blockIdx.x * blockDim.x + threadIdx.x;
    if (i > 3 * X_ROWS) return;
    if (i == 3 * X_ROWS) { out[OFF_NN] = (float)NUM_NODES; return; }
    int r = i / X_ROWS;
    int j = i - r * X_ROWS;
    int node, colv, tabv;
    if (j < NCOLS * N_U) {
        node = j % N_U; colv = j / N_U; tabv = 0;
    } else {
        int jj = j - NCOLS * N_U;
        node = N_U + jj % N_O; colv = NCOLS + jj / N_O; tabv = 1;
    }
    if      (r == 0) out[OFF_NODE + j] = (float)node;
    else if (r == 1) out[OFF_COL  + j] = (float)colv;
    else             out[OFF_TAB  + j] = (float)tabv;
}

// ---------------- num + cat tokens ----------------
__global__ void tok_kernel(
    const float* __restrict__ unum, const int* __restrict__ ucat,
    const float* __restrict__ onum, const int* __restrict__ ocat,
    const float* __restrict__ u_nw, const float* __restrict__ u_nb,
    const float* __restrict__ u_ct, const float* __restrict__ u_col,
    const float* __restrict__ o_nw, const float* __restrict__ o_nb,
    const float* __restrict__ o_ct, const float* __restrict__ o_col,
    const float* __restrict__ temb, float* __restrict__ out)
{
    int rid = blockIdx.x * 4 + (threadIdx.x >> 6);
    int c4 = (threadIdx.x & 63) * 4;
    int k, n, row;
    const float *nw, *nb, *ct, *col, *te, *nump;
    const int* catp;
    if (rid < 6 * N_U) {
        k = rid / N_U; n = rid - k * N_U;
        row = k * N_U + n;
        nw = u_nw; nb = u_nb; ct = u_ct; col = u_col; te = temb;
        nump = unum; catp = ucat;
    } else {
        int b = rid - 6 * N_U;
        k = b / N_O; n = b - k * N_O;
        row = NCOLS * N_U + k * N_O + n;
        nw = o_nw; nb = o_nb; ct = o_ct; col = o_col; te = temb + CDIM;
        nump = onum; catp = ocat;
    }
    float4 v;
    if (k < 3) {
        float x = nump[n * 3 + k];
        float4 w = *(const float4*)&nw[k * CDIM + c4];
        float4 bb = *(const float4*)&nb[k * CDIM + c4];
        float z0 = x * w.x + bb.x, z1 = x * w.y + bb.y;
        float z2 = x * w.z + bb.z, z3 = x * w.w + bb.w;
        v.x = z0 / (1.0f + __expf(-z0));
        v.y = z1 / (1.0f + __expf(-z1));
        v.z = z2 / (1.0f + __expf(-z2));
        v.w = z3 / (1.0f + __expf(-z3));
    } else {
        int idx = catp[n * 3 + (k - 3)];
        v = *(const float4*)&ct[((k - 3) * VOCAB + idx) * CDIM + c4];
    }
    float4 cv = *(const float4*)&col[k * CDIM + c4];
    float4 tv = *(const float4*)&te[c4];
    v.x += cv.x + tv.x; v.y += cv.y + tv.y;
    v.z += cv.z + tv.z; v.w += cv.w + tv.w;
    *(float4*)&out[(size_t)row * CDIM + c4] = v;
}

// ---------------- persistent fp16 HMMA text GEMM (128x128 tile, 2 CTAs/SM) ----------------
// 256 threads, warps 4(m) x 2(n), warp tile 32x64. 472 work items = (tile, half),
// grid 296, 2 CTAs/SM. BK=64. A: each thread loads 32 fp32 (row tid>>1,
// cols (tid&1)*32..+32) -> full 128x64 coverage. B: cp.async 3-stage (2 ahead).
#define U_TILES 157
#define O_TILES 79
#define NTILES  (U_TILES + O_TILES)
#define NWORK   (NTILES * 2)             // 472
#define GEMM_GRID 296
#define BK      64
#define ROWB    144                      // 128B data + 16B pad
#define TILEB_A (128 * ROWB)             // 18432
#define TILEB_B (128 * ROWB)             // 18432
#define SM_B0   (2 * TILEB_A)            // 36864
#define SM_BIAS (SM_B0 + 3 * TILEB_B)    // 92160
#define SM_TOT  (SM_BIAS + 512)          // 92672 (x2 CTAs < 227KB)
#define KCH     (TXTD / BK)              // 24

__global__ void __launch_bounds__(256, 2) txt_gemm_mma(
    const float* __restrict__ uA, const float* __restrict__ oA,
    const float* __restrict__ u_tb, const float* __restrict__ u_col,
    const float* __restrict__ o_tb, const float* __restrict__ o_col,
    const float* __restrict__ temb, float* __restrict__ out)
{
    extern __shared__ char smem[];
    uint32_t sb = smem_u32(smem);

    int tid = threadIdx.x;
    int lane = tid & 31;
    int wid = tid >> 5;
    int warp_m = wid & 3;        // 0..3 -> 32-row slice
    int warp_n = wid >> 2;       // 0..1 -> 64-col slice

    // A load geometry: row = tid>>1 (0..127), 32 fp32 at (tid&1)*32
    int a_r   = tid >> 1;
    int a_c32 = (tid & 1) * 32;
    uint32_t a_sts = (uint32_t)(a_r * ROWB + a_c32 * 2);

    // B load geometry: 4 groups of 16B per thread (128 rows x 128B = 1024 groups)
    int rB[4], csB[4];
    uint32_t dB[4];
    #pragma unroll
    for (int k = 0; k < 4; k++) {
        int g = tid + k * 256;
        rB[k] = g >> 3; csB[k] = g & 7;
        dB[k] = (uint32_t)(rB[k] * ROWB + csB[k] * 16);
    }

    // ldmatrix lane-invariant offsets
    uint32_t a_row = (uint32_t)(warp_m * 32 + (lane & 15));
    uint32_t a_ch  = (uint32_t)(lane >> 4);
    uint32_t b_row = (uint32_t)(warp_n * 64 + (lane & 7) + ((lane >> 4) << 3));
    uint32_t b_ch  = (uint32_t)((lane >> 3) & 1);

    float* s_bias = (float*)(smem + SM_BIAS);

    for (int work = blockIdx.x; work < NWORK; work += GEMM_GRID) {
        int tile = work >> 1;
        int half = work & 1;

        const float* A;
        int M, m0, orow0, wrow0;
        const float *tb, *col, *te;
        if (tile < U_TILES) {
            A = uA; M = N_U; m0 = tile * 128; orow0 = 6 * N_U; wrow0 = 0;
            tb = u_tb; col = u_col; te = temb;
        } else {
            A = oA; M = N_O; m0 = (tile - U_TILES) * 128;
            orow0 = NCOLS * N_U + 6 * N_O; wrow0 = CDIM;
            tb = o_tb; col = o_col; te = temb + CDIM;
        }
        int ncol0 = half * 128;
        int brow0 = wrow0 + ncol0;

        if (tid < 128) {
            int c = ncol0 + tid;
            s_bias[tid] = tb[c] + col[6 * CDIM + c] + te[c];
        }

        float acc[2][8][4];
        #pragma unroll
        for (int mi = 0; mi < 2; mi++)
            #pragma unroll
            for (int nt = 0; nt < 8; nt++)
                #pragma unroll
                for (int q = 0; q < 4; q++) acc[mi][nt][q] = 0.0f;

        int a_gr = m0 + a_r;
        bool a_ok = (a_gr < M);
        const float* a_ptr = A + (size_t)(a_ok ? a_gr : 0) * TXTD + a_c32;

        size_t boff[4];
        #pragma unroll
        for (int k = 0; k < 4; k++)
            boff[k] = (size_t)(brow0 + rB[k]) * TXTD + csB[k] * 8;

        auto load_B = [&](int s, int ch) {
            int k0 = ch * BK;
            uint32_t base = sb + SM_B0 + s * TILEB_B;
            #pragma unroll
            for (int k = 0; k < 4; k++)
                cp16(base + dB[k], &g_w_h[boff[k] + k0], 16);
            CP_COMMIT();
        };

        // prefetch A chunk 0 (32 fp32 = 8 float4) + B chunks 0,1
        float4 av[8];
        {
            const float4* p = (const float4*)a_ptr;
            if (a_ok) {
                #pragma unroll
                for (int q = 0; q < 8; q++) av[q] = p[q];
            } else {
                #pragma unroll
                for (int q = 0; q < 8; q++) av[q] = make_float4(0.f, 0.f, 0.f, 0.f);
            }
        }
        load_B(0, 0);
        load_B(1, 1);

        for (int ch = 0; ch < KCH; ch++) {
            int as_ = ch & 1;
            int bs  = ch % 3;
            if (ch + 1 < KCH) { CP_WAIT1(); }   // B(ch) landed, B(ch+1) may fly
            else              { CP_WAIT0(); }

            // convert prefetched A (32 fp32) -> fp16 SMEM (stage as_)
            {
                uint32_t base = sb + as_ * TILEB_A + a_sts;
                #pragma unroll
                for (int q = 0; q < 4; q++) {
                    __half2 h0 = __floats2half2_rn(av[2*q].x,   av[2*q].y);
                    __half2 h1 = __floats2half2_rn(av[2*q].z,   av[2*q].w);
                    __half2 h2 = __floats2half2_rn(av[2*q+1].x, av[2*q+1].y);
                    __half2 h3 = __floats2half2_rn(av[2*q+1].z, av[2*q+1].w);
                    asm volatile("st.shared.v4.b32 [%0], {%1,%2,%3,%4};" ::
                        "r"(base + q * 16),
                        "r"(*reinterpret_cast<uint32_t*>(&h0)),
                        "r"(*reinterpret_cast<uint32_t*>(&h1)),
                        "r"(*reinterpret_cast<uint32_t*>(&h2)),
                        "r"(*reinterpret_cast<uint32_t*>(&h3)));
                }
            }
            // prefetch A for next chunk
            if (ch + 1 < KCH) {
                const float4* p = (const float4*)(a_ptr + (ch + 1) * BK);
                if (a_ok) {
                    #pragma unroll
                    for (int q = 0; q < 8; q++) av[q] = p[q];
                }
            }
            __syncthreads();   // A(as_) visible; all warps done MMAs of ch-1

            // stage (ch+2)%3 last read at chunk ch-1 -> safe to overwrite now
            if (ch + 2 < KCH) load_B((ch + 2) % 3, ch + 2);

            uint32_t sa  = sb + as_ * TILEB_A;
            uint32_t sbh = sb + SM_B0 + bs * TILEB_B;

            #pragma unroll
            for (int ks = 0; ks < 4; ks++) {
                uint32_t a_off = a_row * ROWB + (2 * ks + a_ch) * 16;
                uint32_t b_off = b_row * ROWB + (2 * ks + b_ch) * 16;

                uint32_t ah[2][4], bh[4][4];
                #pragma unroll
                for (int mi = 0; mi < 2; mi++)
                    LDSM_X4(ah[mi][0], ah[mi][1], ah[mi][2], ah[mi][3],
                            sa + a_off + mi * 16 * ROWB);
                #pragma unroll
                for (int np = 0; np < 4; np++)
                    LDSM_X4(bh[np][0], bh[np][1], bh[np][2], bh[np][3],
                            sbh + b_off + np * 16 * ROWB);
                #pragma unroll
                for (int mi = 0; mi < 2; mi++)
                    #pragma unroll
                    for (int np = 0; np < 4; np++) {
                        MMA16816H(acc[mi][2 * np],     ah[mi], bh[np][0], bh[np][1]);
                        MMA16816H(acc[mi][2 * np + 1], ah[mi], bh[np][2], bh[np][3]);
                    }
            }
        }

        // epilogue
        #pragma unroll
        for (int mi = 0; mi < 2; mi++) {
            #pragma unroll
            for (int rh = 0; rh < 2; rh++) {
                int row = m0 + warp_m * 32 + mi * 16 + (lane >> 2) + rh * 8;
                if (row >= M) continue;
                size_t rbase = (size_t)(orow0 + row) * CDIM + ncol0;
                #pragma unroll
                for (int nt = 0; nt < 8; nt++) {
                    int cc = warp_n * 64 + nt * 8 + (lane & 3) * 2;
                    float2 o;
                    o.x = acc[mi][nt][rh * 2 + 0] + s_bias[cc];
                    o.y = acc[mi][nt][rh * 2 + 1] + s_bias[cc + 1];
                    *(float2*)&out[rbase + cc] = o;
                }
            }
        }
        __syncthreads();   // protect s_bias and smem stages before next item
    }
}

// ---------------- launch ----------------
extern "C" void kernel_launch(void* const* d_in, const int* in_sizes, int n_in,
                              void* d_out, int out_size) {
    const float* users_num   = (const float*)d_in[0];
    const int*   users_cat   = (const int*)  d_in[1];
    const float* users_text  = (const float*)d_in[2];
    const float* orders_num  = (const float*)d_in[3];
    const int*   orders_cat  = (const int*)  d_in[4];
    const float* orders_text = (const float*)d_in[5];
    const int*   edge_index  = (const int*)  d_in[6];
    const float* table_emb   = (const float*)d_in[7];
    const float* u_num_w     = (const float*)d_in[8];
    const float* u_num_b     = (const float*)d_in[9];
    const float* u_cat_tab   = (const float*)d_in[10];
    const float* u_txt_w     = (const float*)d_in[11];
    const float* u_txt_b     = (const float*)d_in[12];
    const float* u_col       = (const float*)d_in[13];
    const float* o_num_w     = (const float*)d_in[14];
    const float* o_num_b     = (const float*)d_in[15];
    const float* o_cat_tab   = (const float*)d_in[16];
    const float* o_txt_w     = (const float*)d_in[17];
    const float* o_txt_b     = (const float*)d_in[18];
    const float* o_col       = (const float*)d_in[19];

    float* out = (float*)d_out;

    // one-time host-side setup (no device allocations)
    static cudaStream_t s2 = nullptr;
    static cudaEvent_t evFork = nullptr, evJoin = nullptr;
    static bool setup_done = false;
    if (!setup_done) {
        cudaFuncSetAttribute(txt_gemm_mma, cudaFuncAttributeMaxDynamicSharedMemorySize, SM_TOT);
        if (cudaStreamCreateWithFlags(&s2, cudaStreamNonBlocking) != cudaSuccess) s2 = nullptr;
        if (s2) {
            cudaEventCreateWithFlags(&evFork, cudaEventDisableTiming);
            cudaEventCreateWithFlags(&evJoin, cudaEventDisableTiming);
        }
        setup_done = true;
    }

    cudaStream_t side = s2 ? s2 : (cudaStream_t)0;
    if (s2) {
        cudaEventRecord(evFork, 0);
        cudaStreamWaitEvent(s2, evFork, 0);
    }

    // ---- side branch: edge table, gathers, indices, tokens ----
    init_scratch_kernel<<<(NUM_NODES * MAXP + 255) / 256, 256, 0, side>>>();
    edge_scatter_kernel<<<(E_EDGES + 255) / 256, 256, 0, side>>>(edge_index);
    edge_sort_write_kernel<<<(N_O + 255) / 256, 256, 0, side>>>(edge_index);
    f2p_gather_kernel<<<(X_ROWS * MAXP + 255) / 256, 256, 0, side>>>(out);
    index_kernel<<<(3 * X_ROWS + 1 + 255) / 256, 256, 0, side>>>(out);
    tok_kernel<<<(6 * N_U + 6 * N_O) / 4, 256, 0, side>>>(
        users_num, users_cat, orders_num, orders_cat,
        u_num_w, u_num_b, u_cat_tab, u_col,
        o_num_w, o_num_b, o_cat_tab, o_col,
        table_emb, out);
    if (s2) cudaEventRecord(evJoin, s2);

    // ---- main branch: W fp16 + fused GEMM ----
    w_h_kernel<<<(CDIM * TXTD + 255) / 256, 256>>>(u_txt_w, o_txt_w);
    txt_gemm_mma<<<GEMM_GRID, 256, SM_TOT>>>(
        users_text, orders_text,
        u_txt_b, u_col, o_txt_b, o_col, table_emb, out);

    if (s2) cudaStreamWaitEvent(0, evJoin, 0);
}

// round 14
// speedup vs baseline: 1.2678x; 1.2678x over previous
#include <cuda_runtime.h>
#include <cuda_fp16.h>
#include <cstdint>

// ---------------- problem constants ----------------
#define N_U      20000
#define N_O      10000
#define N_TOT    30000
#define CDIM     256
#define TXTD     1536
#define NCOLS    7
#define E_EDGES  10000
#define MAXP     16
#define NUM_NODES 30000
#define VOCAB    101

#define X_ROWS   210000
#define OFF_NODE 53760000
#define OFF_COL  53970000
#define OFF_TAB  54180000
#define OFF_F2P  54390000
#define OFF_NN   57750000

// ---------------- device scratch ----------------
__device__ int g_tbl[NUM_NODES * MAXP];
__device__ int g_cnt[N_O];
__device__ int g_slot[N_O * 32];
__device__ __half g_w_h[2 * CDIM * TXTD];   // W rounded to fp16

// ---------------- helpers ----------------
__device__ __forceinline__ uint32_t smem_u32(const void* p) {
    uint32_t a;
    asm("{ .reg .u64 t; cvta.to.shared.u64 t, %1; cvt.u32.u64 %0, t; }" : "=r"(a) : "l"(p));
    return a;
}

#define LDSM_X4(r0, r1, r2, r3, addr) \
    asm volatile("ldmatrix.sync.aligned.m8n8.x4.shared.b16 {%0,%1,%2,%3}, [%4];" \
        : "=r"(r0), "=r"(r1), "=r"(r2), "=r"(r3) : "r"(addr))

#define MMA16816H(d, a, b0, b1) \
    asm volatile("mma.sync.aligned.m16n8k16.row.col.f32.f16.f16.f32 " \
        "{%0,%1,%2,%3}, {%4,%5,%6,%7}, {%8,%9}, {%0,%1,%2,%3};" \
        : "+f"((d)[0]), "+f"((d)[1]), "+f"((d)[2]), "+f"((d)[3]) \
        : "r"((a)[0]), "r"((a)[1]), "r"((a)[2]), "r"((a)[3]), "r"(b0), "r"(b1))

__device__ __forceinline__ void cp16(uint32_t dst, const void* src, int pred_sz) {
    asm volatile("cp.async.cg.shared.global [%0], [%1], 16, %2;"
                 :: "r"(dst), "l"(src), "r"(pred_sz));
}
#define CP_COMMIT() asm volatile("cp.async.commit_group;" ::: "memory")
#define CP_WAIT1()  asm volatile("cp.async.wait_group 1;" ::: "memory")
#define CP_WAIT0()  asm volatile("cp.async.wait_group 0;" ::: "memory")

// ---------------- init scratch ----------------
__global__ void init_scratch_kernel() {
    int i = blockIdx.x * blockDim.x + threadIdx.x;
    if (i < NUM_NODES * MAXP) g_tbl[i] = -1;
    if (i < N_O) g_cnt[i] = 0;
}

// ---------------- W -> fp16 ----------------
__global__ void w_h_kernel(const float* __restrict__ uw, const float* __restrict__ ow) {
    int i = blockIdx.x * blockDim.x + threadIdx.x;
    if (i >= CDIM * TXTD) return;
    int idx = i * 2;
    float a, b;
    if (idx < CDIM * TXTD) { a = uw[idx]; b = uw[idx + 1]; }
    else { a = ow[idx - CDIM * TXTD]; b = ow[idx - CDIM * TXTD + 1]; }
    __half2 h = __floats2half2_rn(a, b);
    *(uint32_t*)&g_w_h[idx] = *reinterpret_cast<uint32_t*>(&h);
}

// ---------------- edges: scatter + per-child sort ----------------
__global__ void edge_scatter_kernel(const int* __restrict__ edge_index) {
    int i = blockIdx.x * blockDim.x + threadIdx.x;
    if (i >= E_EDGES) return;
    int c = edge_index[i];
    int s = atomicAdd(&g_cnt[c], 1);
    if (s < 32) g_slot[c * 32 + s] = i;
}

__global__ void edge_sort_write_kernel(const int* __restrict__ edge_index) {
    int c = blockIdx.x * blockDim.x + threadIdx.x;
    if (c >= N_O) return;
    int n = g_cnt[c];
    if (n > 32) n = 32;
    int idx[32];
    for (int j = 0; j < n; j++) {
        int v = g_slot[c * 32 + j];
        int pos = j;
        while (pos > 0 && idx[pos - 1] > v) { idx[pos] = idx[pos - 1]; pos--; }
        idx[pos] = v;
    }
    int lim = n < MAXP ? n : MAXP;
    for (int r = 0; r < lim; r++)
        g_tbl[(N_U + c) * MAXP + r] = edge_index[E_EDGES + idx[r]];
}

// ---------------- f2p gather ----------------
__global__ void f2p_gather_kernel(float* __restrict__ out) {
    int i = blockIdx.x * blockDim.x + threadIdx.x;
    if (i >= X_ROWS * MAXP) return;
    int row = i >> 4;
    int s = i & (MAXP - 1);
    int node;
    if (row < NCOLS * N_U) node = row % N_U;
    else                   node = N_U + (row - NCOLS * N_U) % N_O;
    out[OFF_F2P + i] = (float)g_tbl[node * MAXP + s];
}

// ---------------- index arrays + num_nodes ----------------
__global__ void index_kernel(float* __restrict__ out) {
    int i = blockIdx.x * blockDim.x + threadIdx.x;
    if (i > 3 * X_ROWS) return;
    if (i == 3 * X_ROWS) { out[OFF_NN] = (float)NUM_NODES; return; }
    int r = i / X_ROWS;
    int j = i - r * X_ROWS;
    int node, colv, tabv;
    if (j < NCOLS * N_U) {
        node = j % N_U; colv = j / N_U; tabv = 0;
    } else {
        int jj = j - NCOLS * N_U;
        node = N_U + jj % N_O; colv = NCOLS + jj / N_O; tabv = 1;
    }
    if      (r == 0) out[OFF_NODE + j] = (float)node;
    else if (r == 1) out[OFF_COL  + j] = (float)colv;
    else             out[OFF_TAB  + j] = (float)tabv;
}

// ---------------- num + cat tokens ----------------
__global__ void tok_kernel(
    const float* __restrict__ unum, const int* __restrict__ ucat,
    const float* __restrict__ onum, const int* __restrict__ ocat,
    const float* __restrict__ u_nw, const float* __restrict__ u_nb,
    const float* __restrict__ u_ct, const float* __restrict__ u_col,
    const float* __restrict__ o_nw, const float* __restrict__ o_nb,
    const float* __restrict__ o_ct, const float* __restrict__ o_col,
    const float* __restrict__ temb, float* __restrict__ out)
{
    int rid = blockIdx.x * 4 + (threadIdx.x >> 6);
    int c4 = (threadIdx.x & 63) * 4;
    int k, n, row;
    const float *nw, *nb, *ct, *col, *te, *nump;
    const int* catp;
    if (rid < 6 * N_U) {
        k = rid / N_U; n = rid - k * N_U;
        row = k * N_U + n;
        nw = u_nw; nb = u_nb; ct = u_ct; col = u_col; te = temb;
        nump = unum; catp = ucat;
    } else {
        int b = rid - 6 * N_U;
        k = b / N_O; n = b - k * N_O;
        row = NCOLS * N_U + k * N_O + n;
        nw = o_nw; nb = o_nb; ct = o_ct; col = o_col; te = temb + CDIM;
        nump = onum; catp = ocat;
    }
    float4 v;
    if (k < 3) {
        float x = nump[n * 3 + k];
        float4 w = *(const float4*)&nw[k * CDIM + c4];
        float4 bb = *(const float4*)&nb[k * CDIM + c4];
        float z0 = x * w.x + bb.x, z1 = x * w.y + bb.y;
        float z2 = x * w.z + bb.z, z3 = x * w.w + bb.w;
        v.x = z0 / (1.0f + __expf(-z0));
        v.y = z1 / (1.0f + __expf(-z1));
        v.z = z2 / (1.0f + __expf(-z2));
        v.w = z3 / (1.0f + __expf(-z3));
    } else {
        int idx = catp[n * 3 + (k - 3)];
        v = *(const float4*)&ct[((k - 3) * VOCAB + idx) * CDIM + c4];
    }
    float4 cv = *(const float4*)&col[k * CDIM + c4];
    float4 tv = *(const float4*)&te[c4];
    v.x += cv.x + tv.x; v.y += cv.y + tv.y;
    v.z += cv.z + tv.z; v.w += cv.w + tv.w;
    *(float4*)&out[(size_t)row * CDIM + c4] = v;
}

// ---------------- persistent fp16 HMMA text GEMM (R11 config + A-ahead staging) ----------------
// 512 threads, CTA tile 128x256, warps 4(m) x 4(n), warp tile 32x64, grid 148.
// BK=64. A staged ONE CHUNK AHEAD: at chunk ch (after barrier) we cvt+STS the
// A for chunk ch+1 into stage (ch+1)&1, so MMAs start right after the barrier.
// B: cp.async 3-stage, issued 2 chunks ahead.
#define U_TILES 157
#define O_TILES 79
#define NTILES  (U_TILES + O_TILES)
#define GEMM_GRID 148
#define BK      64
#define ROWB    144                      // 128B data + 16B pad (conflict-free LDSM)
#define TILEB_A (128 * ROWB)             // 18432
#define TILEB_B (256 * ROWB)             // 36864
#define SM_B0   (2 * TILEB_A)
#define SM_BIAS (2 * TILEB_A + 3 * TILEB_B)   // 147456
#define SM_TOT  (SM_BIAS + 1024)
#define KCH     (TXTD / BK)              // 24

__global__ void __launch_bounds__(512, 1) txt_gemm_mma(
    const float* __restrict__ uA, const float* __restrict__ oA,
    const float* __restrict__ u_tb, const float* __restrict__ u_col,
    const float* __restrict__ o_tb, const float* __restrict__ o_col,
    const float* __restrict__ temb, float* __restrict__ out)
{
    extern __shared__ char smem[];
    uint32_t sb = smem_u32(smem);

    int tid = threadIdx.x;
    int lane = tid & 31;
    int wid = tid >> 5;
    int warp_m = wid & 3;        // 0..3 -> 32-row slice
    int warp_n = wid >> 2;       // 0..3 -> 64-col slice

    // A load geometry: row = tid>>2 (0..127), 16 fp32 at (tid&3)*16
    int a_r   = tid >> 2;
    int a_c16 = (tid & 3) * 16;
    uint32_t a_sts = (uint32_t)(a_r * ROWB + a_c16 * 2);

    // B load geometry: 4 groups of 16B per thread (256 rows x 128B)
    int rB[4], csB[4];
    uint32_t dB[4];
    #pragma unroll
    for (int k = 0; k < 4; k++) {
        int g = tid + k * 512;
        rB[k] = g >> 3; csB[k] = g & 7;
        dB[k] = (uint32_t)(rB[k] * ROWB + csB[k] * 16);
    }

    // ldmatrix lane-invariant offsets
    uint32_t a_row = (uint32_t)(warp_m * 32 + (lane & 15));
    uint32_t a_ch  = (uint32_t)(lane >> 4);
    uint32_t b_row = (uint32_t)(warp_n * 64 + (lane & 7) + ((lane >> 4) << 3));
    uint32_t b_ch  = (uint32_t)((lane >> 3) & 1);

    float* s_bias = (float*)(smem + SM_BIAS);

    for (int tile = blockIdx.x; tile < NTILES; tile += GEMM_GRID) {
        const float* A;
        int M, m0, orow0, wrow0;
        const float *tb, *col, *te;
        if (tile < U_TILES) {
            A = uA; M = N_U; m0 = tile * 128; orow0 = 6 * N_U; wrow0 = 0;
            tb = u_tb; col = u_col; te = temb;
        } else {
            A = oA; M = N_O; m0 = (tile - U_TILES) * 128;
            orow0 = NCOLS * N_U + 6 * N_O; wrow0 = CDIM;
            tb = o_tb; col = o_col; te = temb + CDIM;
        }

        if (tid < 256) {
            s_bias[tid] = tb[tid] + col[6 * CDIM + tid] + te[tid];
        }

        float acc[2][8][4];
        #pragma unroll
        for (int mi = 0; mi < 2; mi++)
            #pragma unroll
            for (int nt = 0; nt < 8; nt++)
                #pragma unroll
                for (int q = 0; q < 4; q++) acc[mi][nt][q] = 0.0f;

        int a_gr = m0 + a_r;
        bool a_ok = (a_gr < M);
        const float* a_ptr = A + (size_t)(a_ok ? a_gr : 0) * TXTD + a_c16;

        size_t boff[4];
        #pragma unroll
        for (int k = 0; k < 4; k++)
            boff[k] = (size_t)(wrow0 + rB[k]) * TXTD + csB[k] * 8;

        auto load_B = [&](int s, int ch) {
            int k0 = ch * BK;
            uint32_t base = sb + SM_B0 + s * TILEB_B;
            #pragma unroll
            for (int k = 0; k < 4; k++)
                cp16(base + dB[k], &g_w_h[boff[k] + k0], 16);
            CP_COMMIT();
        };

        auto stage_A = [&](int s, const float4* p) {
            uint32_t base = sb + s * TILEB_A + a_sts;
            float4 v0 = p[0], v1 = p[1], v2 = p[2], v3 = p[3];
            __half2 h0 = __floats2half2_rn(v0.x, v0.y);
            __half2 h1 = __floats2half2_rn(v0.z, v0.w);
            __half2 h2 = __floats2half2_rn(v1.x, v1.y);
            __half2 h3 = __floats2half2_rn(v1.z, v1.w);
            asm volatile("st.shared.v4.b32 [%0], {%1,%2,%3,%4};" ::
                "r"(base),
                "r"(*reinterpret_cast<uint32_t*>(&h0)),
                "r"(*reinterpret_cast<uint32_t*>(&h1)),
                "r"(*reinterpret_cast<uint32_t*>(&h2)),
                "r"(*reinterpret_cast<uint32_t*>(&h3)));
            __half2 h4 = __floats2half2_rn(v2.x, v2.y);
            __half2 h5 = __floats2half2_rn(v2.z, v2.w);
            __half2 h6 = __floats2half2_rn(v3.x, v3.y);
            __half2 h7 = __floats2half2_rn(v3.z, v3.w);
            asm volatile("st.shared.v4.b32 [%0], {%1,%2,%3,%4};" ::
                "r"(base + 16),
                "r"(*reinterpret_cast<uint32_t*>(&h4)),
                "r"(*reinterpret_cast<uint32_t*>(&h5)),
                "r"(*reinterpret_cast<uint32_t*>(&h6)),
                "r"(*reinterpret_cast<uint32_t*>(&h7)));
        };

        // prologue: A[0] -> regs -> stage 0; A[1] -> regs; B chunks 0,1 in flight
        float4 av[4];
        {
            const float4* p = (const float4*)a_ptr;
            if (a_ok) { av[0] = p[0]; av[1] = p[1]; av[2] = p[2]; av[3] = p[3]; }
            else { av[0] = av[1] = av[2] = av[3] = make_float4(0.f, 0.f, 0.f, 0.f); }
            stage_A(0, av);
            const float4* p1 = (const float4*)(a_ptr + BK);
            if (a_ok) { av[0] = p1[0]; av[1] = p1[1]; av[2] = p1[2]; av[3] = p1[3]; }
        }
        load_B(0, 0);
        load_B(1, 1);

        for (int ch = 0; ch < KCH; ch++) {
            int as_ = ch & 1;
            int bs  = ch % 3;
            if (ch + 1 < KCH) { CP_WAIT1(); }   // B(ch) landed, B(ch+1) may fly
            else              { CP_WAIT0(); }
            __syncthreads();   // A(as_) [staged at ch-1] visible; MMAs of ch-1 done

            // B stage (ch+2)%3 last read at ch-1 -> safe to overwrite now
            if (ch + 2 < KCH) load_B((ch + 2) % 3, ch + 2);

            // stage A for NEXT chunk into stage as_^1 (its last readers were
            // MMAs of ch-1, already done per this barrier), then prefetch A(ch+2)
            if (ch + 1 < KCH) {
                stage_A(as_ ^ 1, av);
                if (ch + 2 < KCH) {
                    const float4* p = (const float4*)(a_ptr + (ch + 2) * BK);
                    if (a_ok) { av[0] = p[0]; av[1] = p[1]; av[2] = p[2]; av[3] = p[3]; }
                }
            }

            uint32_t sa  = sb + as_ * TILEB_A;
            uint32_t sbh = sb + SM_B0 + bs * TILEB_B;

            #pragma unroll
            for (int ks = 0; ks < 4; ks++) {
                uint32_t a_off = a_row * ROWB + (2 * ks + a_ch) * 16;
                uint32_t b_off = b_row * ROWB + (2 * ks + b_ch) * 16;

                uint32_t ah[2][4], bh[4][4];
                #pragma unroll
                for (int mi = 0; mi < 2; mi++)
                    LDSM_X4(ah[mi][0], ah[mi][1], ah[mi][2], ah[mi][3],
                            sa + a_off + mi * 16 * ROWB);
                #pragma unroll
                for (int np = 0; np < 4; np++)
                    LDSM_X4(bh[np][0], bh[np][1], bh[np][2], bh[np][3],
                            sbh + b_off + np * 16 * ROWB);
                #pragma unroll
                for (int mi = 0; mi < 2; mi++)
                    #pragma unroll
                    for (int np = 0; np < 4; np++) {
                        MMA16816H(acc[mi][2 * np],     ah[mi], bh[np][0], bh[np][1]);
                        MMA16816H(acc[mi][2 * np + 1], ah[mi], bh[np][2], bh[np][3]);
                    }
            }
        }

        // epilogue
        #pragma unroll
        for (int mi = 0; mi < 2; mi++) {
            #pragma unroll
            for (int rh = 0; rh < 2; rh++) {
                int row = m0 + warp_m * 32 + mi * 16 + (lane >> 2) + rh * 8;
                if (row >= M) continue;
                size_t rbase = (size_t)(orow0 + row) * CDIM;
                #pragma unroll
                for (int nt = 0; nt < 8; nt++) {
                    int cc = warp_n * 64 + nt * 8 + (lane & 3) * 2;
                    float2 o;
                    o.x = acc[mi][nt][rh * 2 + 0] + s_bias[cc];
                    o.y = acc[mi][nt][rh * 2 + 1] + s_bias[cc + 1];
                    *(float2*)&out[rbase + cc] = o;
                }
            }
        }
        __syncthreads();   // protect s_bias and smem stages before next tile
    }
}

// ---------------- launch ----------------
extern "C" void kernel_launch(void* const* d_in, const int* in_sizes, int n_in,
                              void* d_out, int out_size) {
    const float* users_num   = (const float*)d_in[0];
    const int*   users_cat   = (const int*)  d_in[1];
    const float* users_text  = (const float*)d_in[2];
    const float* orders_num  = (const float*)d_in[3];
    const int*   orders_cat  = (const int*)  d_in[4];
    const float* orders_text = (const float*)d_in[5];
    const int*   edge_index  = (const int*)  d_in[6];
    const float* table_emb   = (const float*)d_in[7];
    const float* u_num_w     = (const float*)d_in[8];
    const float* u_num_b     = (const float*)d_in[9];
    const float* u_cat_tab   = (const float*)d_in[10];
    const float* u_txt_w     = (const float*)d_in[11];
    const float* u_txt_b     = (const float*)d_in[12];
    const float* u_col       = (const float*)d_in[13];
    const float* o_num_w     = (const float*)d_in[14];
    const float* o_num_b     = (const float*)d_in[15];
    const float* o_cat_tab   = (const float*)d_in[16];
    const float* o_txt_w     = (const float*)d_in[17];
    const float* o_txt_b     = (const float*)d_in[18];
    const float* o_col       = (const float*)d_in[19];

    float* out = (float*)d_out;

    // one-time host-side setup (no device allocations)
    static cudaStream_t s2 = nullptr;
    static cudaEvent_t evFork = nullptr, evJoin = nullptr;
    static bool setup_done = false;
    if (!setup_done) {
        cudaFuncSetAttribute(txt_gemm_mma, cudaFuncAttributeMaxDynamicSharedMemorySize, SM_TOT);
        if (cudaStreamCreateWithFlags(&s2, cudaStreamNonBlocking) != cudaSuccess) s2 = nullptr;
        if (s2) {
            cudaEventCreateWithFlags(&evFork, cudaEventDisableTiming);
            cudaEventCreateWithFlags(&evJoin, cudaEventDisableTiming);
        }
        setup_done = true;
    }

    cudaStream_t side = s2 ? s2 : (cudaStream_t)0;
    if (s2) {
        cudaEventRecord(evFork, 0);
        cudaStreamWaitEvent(s2, evFork, 0);
    }

    // ---- side branch: edge table, gathers, indices, tokens ----
    init_scratch_kernel<<<(NUM_NODES * MAXP + 255) / 256, 256, 0, side>>>();
    edge_scatter_kernel<<<(E_EDGES + 255) / 256, 256, 0, side>>>(edge_index);
    edge_sort_write_kernel<<<(N_O + 255) / 256, 256, 0, side>>>(edge_index);
    f2p_gather_kernel<<<(X_ROWS * MAXP + 255) / 256, 256, 0, side>>>(out);
    index_kernel<<<(3 * X_ROWS + 1 + 255) / 256, 256, 0, side>>>(out);
    tok_kernel<<<(6 * N_U + 6 * N_O) / 4, 256, 0, side>>>(
        users_num, users_cat, orders_num, orders_cat,
        u_num_w, u_num_b, u_cat_tab, u_col,
        o_num_w, o_num_b, o_cat_tab, o_col,
        table_emb, out);
    if (s2) cudaEventRecord(evJoin, s2);

    // ---- main branch: W fp16 + fused GEMM ----
    w_h_kernel<<<(CDIM * TXTD + 255) / 256, 256>>>(u_txt_w, o_txt_w);
    txt_gemm_mma<<<GEMM_GRID, 512, SM_TOT>>>(
        users_text, orders_text,
        u_txt_b, u_col, o_txt_b, o_col, table_emb, out);

    if (s2) cudaStreamWaitEvent(0, evJoin, 0);
}

// round 15
// speedup vs baseline: 1.3023x; 1.0272x over previous
#include <cuda_runtime.h>
#include <cuda_fp16.h>
#include <cstdint>

// ---------------- problem constants ----------------
#define N_U      20000
#define N_O      10000
#define N_TOT    30000
#define CDIM     256
#define TXTD     1536
#define NCOLS    7
#define E_EDGES  10000
#define MAXP     16
#define NUM_NODES 30000
#define VOCAB    101

#define X_ROWS   210000
#define OFF_NODE 53760000
#define OFF_COL  53970000
#define OFF_TAB  54180000
#define OFF_F2P  54390000
#define OFF_NN   57750000

// ---------------- device scratch ----------------
__device__ int g_tbl[NUM_NODES * MAXP];
__device__ int g_cnt[N_O];
__device__ int g_slot[N_O * 32];
__device__ __half g_w_h[2 * CDIM * TXTD];   // W rounded to fp16

// ---------------- helpers ----------------
__device__ __forceinline__ uint32_t smem_u32(const void* p) {
    uint32_t a;
    asm("{ .reg .u64 t; cvta.to.shared.u64 t, %1; cvt.u32.u64 %0, t; }" : "=r"(a) : "l"(p));
    return a;
}

#define LDSM_X4(r0, r1, r2, r3, addr) \
    asm volatile("ldmatrix.sync.aligned.m8n8.x4.shared.b16 {%0,%1,%2,%3}, [%4];" \
        : "=r"(r0), "=r"(r1), "=r"(r2), "=r"(r3) : "r"(addr))

#define MMA16816H(d, a, b0, b1) \
    asm volatile("mma.sync.aligned.m16n8k16.row.col.f32.f16.f16.f32 " \
        "{%0,%1,%2,%3}, {%4,%5,%6,%7}, {%8,%9}, {%0,%1,%2,%3};" \
        : "+f"((d)[0]), "+f"((d)[1]), "+f"((d)[2]), "+f"((d)[3]) \
        : "r"((a)[0]), "r"((a)[1]), "r"((a)[2]), "r"((a)[3]), "r"(b0), "r"(b1))

__device__ __forceinline__ void cp16(uint32_t dst, const void* src, int pred_sz) {
    asm volatile("cp.async.cg.shared.global [%0], [%1], 16, %2;"
                 :: "r"(dst), "l"(src), "r"(pred_sz));
}
#define CP_COMMIT() asm volatile("cp.async.commit_group;" ::: "memory")
#define CP_WAIT1()  asm volatile("cp.async.wait_group 1;" ::: "memory")
#define CP_WAIT0()  asm volatile("cp.async.wait_group 0;" ::: "memory")

// ---------------- init scratch ----------------
__global__ void init_scratch_kernel() {
    int i = blockIdx.x * blockDim.x + threadIdx.x;
    if (i < NUM_NODES * MAXP) g_tbl[i] = -1;
    if (i < N_O) g_cnt[i] = 0;
}

// ---------------- W -> fp16 ----------------
__global__ void w_h_kernel(const float* __restrict__ uw, const float* __restrict__ ow) {
    int i = blockIdx.x * blockDim.x + threadIdx.x;
    if (i >= CDIM * TXTD) return;
    int idx = i * 2;
    float a, b;
    if (idx < CDIM * TXTD) { a = uw[idx]; b = uw[idx + 1]; }
    else { a = ow[idx - CDIM * TXTD]; b = ow[idx - CDIM * TXTD + 1]; }
    __half2 h = __floats2half2_rn(a, b);
    *(uint32_t*)&g_w_h[idx] = *reinterpret_cast<uint32_t*>(&h);
}

// ---------------- edges: scatter + per-child sort ----------------
__global__ void edge_scatter_kernel(const int* __restrict__ edge_index) {
    int i = blockIdx.x * blockDim.x + threadIdx.x;
    if (i >= E_EDGES) return;
    int c = edge_index[i];
    int s = atomicAdd(&g_cnt[c], 1);
    if (s < 32) g_slot[c * 32 + s] = i;
}

__global__ void edge_sort_write_kernel(const int* __restrict__ edge_index) {
    int c = blockIdx.x * blockDim.x + threadIdx.x;
    if (c >= N_O) return;
    int n = g_cnt[c];
    if (n > 32) n = 32;
    int idx[32];
    for (int j = 0; j < n; j++) {
        int v = g_slot[c * 32 + j];
        int pos = j;
        while (pos > 0 && idx[pos - 1] > v) { idx[pos] = idx[pos - 1]; pos--; }
        idx[pos] = v;
    }
    int lim = n < MAXP ? n : MAXP;
    for (int r = 0; r < lim; r++)
        g_tbl[(N_U + c) * MAXP + r] = edge_index[E_EDGES + idx[r]];
}

// ---------------- f2p gather ----------------
__global__ void f2p_gather_kernel(float* __restrict__ out) {
    int i = blockIdx.x * blockDim.x + threadIdx.x;
    if (i >= X_ROWS * MAXP) return;
    int row = i >> 4;
    int s = i & (MAXP - 1);
    int node;
    if (row < NCOLS * N_U) node = row % N_U;
    else                   node = N_U + (row - NCOLS * N_U) % N_O;
    out[OFF_F2P + i] = (float)g_tbl[node * MAXP + s];
}

// ---------------- index arrays + num_nodes ----------------
__global__ void index_kernel(float* __restrict__ out) {
    int i = blockIdx.x * blockDim.x + threadIdx.x;
    if (i > 3 * X_ROWS) return;
    if (i == 3 * X_ROWS) { out[OFF_NN] = (float)NUM_NODES; return; }
    int r = i / X_ROWS;
    int j = i - r * X_ROWS;
    int node, colv, tabv;
    if (j < NCOLS * N_U) {
        node = j % N_U; colv = j / N_U; tabv = 0;
    } else {
        int jj = j - NCOLS * N_U;
        node = N_U + jj % N_O; colv = NCOLS + jj / N_O; tabv = 1;
    }
    if      (r == 0) out[OFF_NODE + j] = (float)node;
    else if (r == 1) out[OFF_COL  + j] = (float)colv;
    else             out[OFF_TAB  + j] = (float)tabv;
}

// ---------------- num + cat tokens ----------------
__global__ void tok_kernel(
    const float* __restrict__ unum, const int* __restrict__ ucat,
    const float* __restrict__ onum, const int* __restrict__ ocat,
    const float* __restrict__ u_nw, const float* __restrict__ u_nb,
    const float* __restrict__ u_ct, const float* __restrict__ u_col,
    const float* __restrict__ o_nw, const float* __restrict__ o_nb,
    const float* __restrict__ o_ct, const float* __restrict__ o_col,
    const float* __restrict__ temb, float* __restrict__ out)
{
    int rid = blockIdx.x * 4 + (threadIdx.x >> 6);
    int c4 = (threadIdx.x & 63) * 4;
    int k, n, row;
    const float *nw, *nb, *ct, *col, *te, *nump;
    const int* catp;
    if (rid < 6 * N_U) {
        k = rid / N_U; n = rid - k * N_U;
        row = k * N_U + n;
        nw = u_nw; nb = u_nb; ct = u_ct; col = u_col; te = temb;
        nump = unum; catp = ucat;
    } else {
        int b = rid - 6 * N_U;
        k = b / N_O; n = b - k * N_O;
        row = NCOLS * N_U + k * N_O + n;
        nw = o_nw; nb = o_nb; ct = o_ct; col = o_col; te = temb + CDIM;
        nump = onum; catp = ocat;
    }
    float4 v;
    if (k < 3) {
        float x = nump[n * 3 + k];
        float4 w = *(const float4*)&nw[k * CDIM + c4];
        float4 bb = *(const float4*)&nb[k * CDIM + c4];
        float z0 = x * w.x + bb.x, z1 = x * w.y + bb.y;
        float z2 = x * w.z + bb.z, z3 = x * w.w + bb.w;
        v.x = z0 / (1.0f + __expf(-z0));
        v.y = z1 / (1.0f + __expf(-z1));
        v.z = z2 / (1.0f + __expf(-z2));
        v.w = z3 / (1.0f + __expf(-z3));
    } else {
        int idx = catp[n * 3 + (k - 3)];
        v = *(const float4*)&ct[((k - 3) * VOCAB + idx) * CDIM + c4];
    }
    float4 cv = *(const float4*)&col[k * CDIM + c4];
    float4 tv = *(const float4*)&te[c4];
    v.x += cv.x + tv.x; v.y += cv.y + tv.y;
    v.z += cv.z + tv.z; v.w += cv.w + tv.w;
    *(float4*)&out[(size_t)row * CDIM + c4] = v;
}

// ---------------- persistent fp16 HMMA text GEMM (R11 config + boundary prefetch) ----------------
// 512 threads, CTA tile 128x256, warps 4(m) x 4(n), warp tile 32x64, grid 148.
// BK=64. A: fp32 reg-prefetch -> fp16 cvt at chunk top (R11 order).
// B: cp.async 3-stage, 2 chunks ahead. NEW: before each tile's epilogue, the
// NEXT tile's B chunks 0,1 (stages 0,1 -- provably free after barrier(23)) and
// A chunk 0 regs are prefetched so the epilogue hides the prologue latency.
#define U_TILES 157
#define O_TILES 79
#define NTILES  (U_TILES + O_TILES)
#define GEMM_GRID 148
#define BK      64
#define ROWB    144                      // 128B data + 16B pad (conflict-free LDSM)
#define TILEB_A (128 * ROWB)             // 18432
#define TILEB_B (256 * ROWB)             // 36864
#define SM_B0   (2 * TILEB_A)
#define SM_BIAS (2 * TILEB_A + 3 * TILEB_B)   // 147456
#define SM_TOT  (SM_BIAS + 1024)
#define KCH     (TXTD / BK)              // 24

__global__ void __launch_bounds__(512, 1) txt_gemm_mma(
    const float* __restrict__ uA, const float* __restrict__ oA,
    const float* __restrict__ u_tb, const float* __restrict__ u_col,
    const float* __restrict__ o_tb, const float* __restrict__ o_col,
    const float* __restrict__ temb, float* __restrict__ out)
{
    extern __shared__ char smem[];
    uint32_t sb = smem_u32(smem);

    int tid = threadIdx.x;
    int lane = tid & 31;
    int wid = tid >> 5;
    int warp_m = wid & 3;        // 0..3 -> 32-row slice
    int warp_n = wid >> 2;       // 0..3 -> 64-col slice

    // A load geometry: row = tid>>2 (0..127), 16 fp32 at (tid&3)*16
    int a_r   = tid >> 2;
    int a_c16 = (tid & 3) * 16;
    uint32_t a_sts = (uint32_t)(a_r * ROWB + a_c16 * 2);

    // B load geometry: 4 groups of 16B per thread (256 rows x 128B)
    int rB[4], csB[4];
    uint32_t dB[4];
    #pragma unroll
    for (int k = 0; k < 4; k++) {
        int g = tid + k * 512;
        rB[k] = g >> 3; csB[k] = g & 7;
        dB[k] = (uint32_t)(rB[k] * ROWB + csB[k] * 16);
    }

    // ldmatrix lane-invariant offsets
    uint32_t a_row = (uint32_t)(warp_m * 32 + (lane & 15));
    uint32_t a_ch  = (uint32_t)(lane >> 4);
    uint32_t b_row = (uint32_t)(warp_n * 64 + (lane & 7) + ((lane >> 4) << 3));
    uint32_t b_ch  = (uint32_t)((lane >> 3) & 1);

    float* s_bias = (float*)(smem + SM_BIAS);

    // cross-tile prefetch state
    bool pf = false;
    float4 av0, av1, av2, av3;

    for (int tile = blockIdx.x; tile < NTILES; tile += GEMM_GRID) {
        const float* A;
        int M, m0, orow0, wrow0;
        const float *tb, *col, *te;
        if (tile < U_TILES) {
            A = uA; M = N_U; m0 = tile * 128; orow0 = 6 * N_U; wrow0 = 0;
            tb = u_tb; col = u_col; te = temb;
        } else {
            A = oA; M = N_O; m0 = (tile - U_TILES) * 128;
            orow0 = NCOLS * N_U + 6 * N_O; wrow0 = CDIM;
            tb = o_tb; col = o_col; te = temb + CDIM;
        }

        if (tid < 256) {
            s_bias[tid] = tb[tid] + col[6 * CDIM + tid] + te[tid];
        }

        float acc[2][8][4];
        #pragma unroll
        for (int mi = 0; mi < 2; mi++)
            #pragma unroll
            for (int nt = 0; nt < 8; nt++)
                #pragma unroll
                for (int q = 0; q < 4; q++) acc[mi][nt][q] = 0.0f;

        int a_gr = m0 + a_r;
        bool a_ok = (a_gr < M);
        const float* a_ptr = A + (size_t)(a_ok ? a_gr : 0) * TXTD + a_c16;

        size_t boff[4];
        #pragma unroll
        for (int k = 0; k < 4; k++)
            boff[k] = (size_t)(wrow0 + rB[k]) * TXTD + csB[k] * 8;

        auto load_B = [&](int s, int ch) {
            int k0 = ch * BK;
            uint32_t base = sb + SM_B0 + s * TILEB_B;
            #pragma unroll
            for (int k = 0; k < 4; k++)
                cp16(base + dB[k], &g_w_h[boff[k] + k0], 16);
            CP_COMMIT();
        };

        // prologue: A chunk 0 + B chunks 0,1 (skip if prefetched at previous tile's end)
        if (!pf) {
            const float4* p = (const float4*)a_ptr;
            if (a_ok) { av0 = p[0]; av1 = p[1]; av2 = p[2]; av3 = p[3]; }
            else { av0 = av1 = av2 = av3 = make_float4(0.f, 0.f, 0.f, 0.f); }
            load_B(0, 0);
            load_B(1, 1);
        }

        for (int ch = 0; ch < KCH; ch++) {
            int as_ = ch & 1;
            int bs  = ch % 3;
            if (ch + 1 < KCH) { CP_WAIT1(); }   // B(ch) landed, B(ch+1) may fly
            else              { CP_WAIT0(); }

            // convert prefetched A -> fp16 SMEM (stage as_)
            {
                uint32_t base = sb + as_ * TILEB_A;
                __half2 h0 = __floats2half2_rn(av0.x, av0.y);
                __half2 h1 = __floats2half2_rn(av0.z, av0.w);
                __half2 h2 = __floats2half2_rn(av1.x, av1.y);
                __half2 h3 = __floats2half2_rn(av1.z, av1.w);
                asm volatile("st.shared.v4.b32 [%0], {%1,%2,%3,%4};" ::
                    "r"(base + a_sts),
                    "r"(*reinterpret_cast<uint32_t*>(&h0)),
                    "r"(*reinterpret_cast<uint32_t*>(&h1)),
                    "r"(*reinterpret_cast<uint32_t*>(&h2)),
                    "r"(*reinterpret_cast<uint32_t*>(&h3)));
                __half2 h4 = __floats2half2_rn(av2.x, av2.y);
                __half2 h5 = __floats2half2_rn(av2.z, av2.w);
                __half2 h6 = __floats2half2_rn(av3.x, av3.y);
                __half2 h7 = __floats2half2_rn(av3.z, av3.w);
                asm volatile("st.shared.v4.b32 [%0], {%1,%2,%3,%4};" ::
                    "r"(base + a_sts + 16),
                    "r"(*reinterpret_cast<uint32_t*>(&h4)),
                    "r"(*reinterpret_cast<uint32_t*>(&h5)),
                    "r"(*reinterpret_cast<uint32_t*>(&h6)),
                    "r"(*reinterpret_cast<uint32_t*>(&h7)));
            }
            // prefetch A for next chunk
            if (ch + 1 < KCH) {
                const float4* p = (const float4*)(a_ptr + (ch + 1) * BK);
                if (a_ok) { av0 = p[0]; av1 = p[1]; av2 = p[2]; av3 = p[3]; }
            }
            __syncthreads();   // A(as_) visible; all warps done MMAs of ch-1

            // stage (ch+2)%3 last read at chunk ch-1 -> safe to overwrite now
            if (ch + 2 < KCH) load_B((ch + 2) % 3, ch + 2);

            uint32_t sa  = sb + as_ * TILEB_A;
            uint32_t sbh = sb + SM_B0 + bs * TILEB_B;

            #pragma unroll
            for (int ks = 0; ks < 4; ks++) {
                uint32_t a_off = a_row * ROWB + (2 * ks + a_ch) * 16;
                uint32_t b_off = b_row * ROWB + (2 * ks + b_ch) * 16;

                uint32_t ah[2][4], bh[4][4];
                #pragma unroll
                for (int mi = 0; mi < 2; mi++)
                    LDSM_X4(ah[mi][0], ah[mi][1], ah[mi][2], ah[mi][3],
                            sa + a_off + mi * 16 * ROWB);
                #pragma unroll
                for (int np = 0; np < 4; np++)
                    LDSM_X4(bh[np][0], bh[np][1], bh[np][2], bh[np][3],
                            sbh + b_off + np * 16 * ROWB);
                #pragma unroll
                for (int mi = 0; mi < 2; mi++)
                    #pragma unroll
                    for (int np = 0; np < 4; np++) {
                        MMA16816H(acc[mi][2 * np],     ah[mi], bh[np][0], bh[np][1]);
                        MMA16816H(acc[mi][2 * np + 1], ah[mi], bh[np][2], bh[np][3]);
                    }
            }
        }

        // ---- boundary prefetch for NEXT tile (stages 0,1 are free: their last
        // readers were MMAs of chunks 21,22, complete per barrier(23)) ----
        int ntile = tile + GEMM_GRID;
        pf = (ntile < NTILES);
        if (pf) {
            const float* nA;
            int nM, nm0, nwrow0;
            if (ntile < U_TILES) { nA = uA; nM = N_U; nm0 = ntile * 128; nwrow0 = 0; }
            else { nA = oA; nM = N_O; nm0 = (ntile - U_TILES) * 128; nwrow0 = CDIM; }
            // next-tile B chunks 0,1
            {
                uint32_t base0 = sb + SM_B0;               // stage 0
                uint32_t base1 = sb + SM_B0 + TILEB_B;     // stage 1
                #pragma unroll
                for (int k = 0; k < 4; k++) {
                    size_t nb = (size_t)(nwrow0 + rB[k]) * TXTD + csB[k] * 8;
                    cp16(base0 + dB[k], &g_w_h[nb], 16);
                }
                CP_COMMIT();
                #pragma unroll
                for (int k = 0; k < 4; k++) {
                    size_t nb = (size_t)(nwrow0 + rB[k]) * TXTD + csB[k] * 8;
                    cp16(base1 + dB[k], &g_w_h[nb + BK], 16);
                }
                CP_COMMIT();
            }
            // next-tile A chunk 0 into regs
            int na_gr = nm0 + a_r;
            bool na_ok = (na_gr < nM);
            const float4* p = (const float4*)(nA + (size_t)(na_ok ? na_gr : 0) * TXTD + a_c16);
            if (na_ok) { av0 = p[0]; av1 = p[1]; av2 = p[2]; av3 = p[3]; }
            else { av0 = av1 = av2 = av3 = make_float4(0.f, 0.f, 0.f, 0.f); }
        }

        // epilogue (overlaps the boundary prefetch latency)
        #pragma unroll
        for (int mi = 0; mi < 2; mi++) {
            #pragma unroll
            for (int rh = 0; rh < 2; rh++) {
                int row = m0 + warp_m * 32 + mi * 16 + (lane >> 2) + rh * 8;
                if (row >= M) continue;
                size_t rbase = (size_t)(orow0 + row) * CDIM;
                #pragma unroll
                for (int nt = 0; nt < 8; nt++) {
                    int cc = warp_n * 64 + nt * 8 + (lane & 3) * 2;
                    float2 o;
                    o.x = acc[mi][nt][rh * 2 + 0] + s_bias[cc];
                    o.y = acc[mi][nt][rh * 2 + 1] + s_bias[cc + 1];
                    *(float2*)&out[rbase + cc] = o;
                }
            }
        }
        __syncthreads();   // protect s_bias and smem stages before next tile
    }
}

// ---------------- launch ----------------
extern "C" void kernel_launch(void* const* d_in, const int* in_sizes, int n_in,
                              void* d_out, int out_size) {
    const float* users_num   = (const float*)d_in[0];
    const int*   users_cat   = (const int*)  d_in[1];
    const float* users_text  = (const float*)d_in[2];
    const float* orders_num  = (const float*)d_in[3];
    const int*   orders_cat  = (const int*)  d_in[4];
    const float* orders_text = (const float*)d_in[5];
    const int*   edge_index  = (const int*)  d_in[6];
    const float* table_emb   = (const float*)d_in[7];
    const float* u_num_w     = (const float*)d_in[8];
    const float* u_num_b     = (const float*)d_in[9];
    const float* u_cat_tab   = (const float*)d_in[10];
    const float* u_txt_w     = (const float*)d_in[11];
    const float* u_txt_b     = (const float*)d_in[12];
    const float* u_col       = (const float*)d_in[13];
    const float* o_num_w     = (const float*)d_in[14];
    const float* o_num_b     = (const float*)d_in[15];
    const float* o_cat_tab   = (const float*)d_in[16];
    const float* o_txt_w     = (const float*)d_in[17];
    const float* o_txt_b     = (const float*)d_in[18];
    const float* o_col       = (const float*)d_in[19];

    float* out = (float*)d_out;

    // one-time host-side setup (no device allocations)
    static cudaStream_t s2 = nullptr;
    static cudaEvent_t evFork = nullptr, evJoin = nullptr;
    static bool setup_done = false;
    if (!setup_done) {
        cudaFuncSetAttribute(txt_gemm_mma, cudaFuncAttributeMaxDynamicSharedMemorySize, SM_TOT);
        if (cudaStreamCreateWithFlags(&s2, cudaStreamNonBlocking) != cudaSuccess) s2 = nullptr;
        if (s2) {
            cudaEventCreateWithFlags(&evFork, cudaEventDisableTiming);
            cudaEventCreateWithFlags(&evJoin, cudaEventDisableTiming);
        }
        setup_done = true;
    }

    cudaStream_t side = s2 ? s2 : (cudaStream_t)0;
    if (s2) {
        cudaEventRecord(evFork, 0);
        cudaStreamWaitEvent(s2, evFork, 0);
    }

    // ---- side branch: edge table, gathers, indices, tokens ----
    init_scratch_kernel<<<(NUM_NODES * MAXP + 255) / 256, 256, 0, side>>>();
    edge_scatter_kernel<<<(E_EDGES + 255) / 256, 256, 0, side>>>(edge_index);
    edge_sort_write_kernel<<<(N_O + 255) / 256, 256, 0, side>>>(edge_index);
    f2p_gather_kernel<<<(X_ROWS * MAXP + 255) / 256, 256, 0, side>>>(out);
    index_kernel<<<(3 * X_ROWS + 1 + 255) / 256, 256, 0, side>>>(out);
    tok_kernel<<<(6 * N_U + 6 * N_O) / 4, 256, 0, side>>>(
        users_num, users_cat, orders_num, orders_cat,
        u_num_w, u_num_b, u_cat_tab, u_col,
        o_num_w, o_num_b, o_cat_tab, o_col,
        table_emb, out);
    if (s2) cudaEventRecord(evJoin, s2);

    // ---- main branch: W fp16 + fused GEMM ----
    w_h_kernel<<<(CDIM * TXTD + 255) / 256, 256>>>(u_txt_w, o_txt_w);
    txt_gemm_mma<<<GEMM_GRID, 512, SM_TOT>>>(
        users_text, orders_text,
        u_txt_b, u_col, o_txt_b, o_col, table_emb, out);

    if (s2) cudaStreamWaitEvent(0, evJoin, 0);
}

// round 16
// speedup vs baseline: 1.3503x; 1.0368x over previous
#include <cuda_runtime.h>
#include <cuda_fp16.h>
#include <cstdint>

// ---------------- problem constants ----------------
#define N_U      20000
#define N_O      10000
#define N_TOT    30000
#define CDIM     256
#define TXTD     1536
#define NCOLS    7
#define E_EDGES  10000
#define MAXP     16
#define NUM_NODES 30000
#define VOCAB    101

#define X_ROWS   210000
#define OFF_NODE 53760000
#define OFF_COL  53970000
#define OFF_TAB  54180000
#define OFF_F2P  54390000
#define OFF_NN   57750000

// ---------------- device scratch ----------------
__device__ int g_tbl[NUM_NODES * MAXP];
__device__ int g_cnt[N_O];
__device__ int g_slot[N_O * 32];
__device__ __half g_w_h[2 * CDIM * TXTD];   // W rounded to fp16

// ---------------- helpers ----------------
__device__ __forceinline__ uint32_t smem_u32(const void* p) {
    uint32_t a;
    asm("{ .reg .u64 t; cvta.to.shared.u64 t, %1; cvt.u32.u64 %0, t; }" : "=r"(a) : "l"(p));
    return a;
}

#define LDSM_X4(r0, r1, r2, r3, addr) \
    asm volatile("ldmatrix.sync.aligned.m8n8.x4.shared.b16 {%0,%1,%2,%3}, [%4];" \
        : "=r"(r0), "=r"(r1), "=r"(r2), "=r"(r3) : "r"(addr))

#define MMA16816H(d, a, b0, b1) \
    asm volatile("mma.sync.aligned.m16n8k16.row.col.f32.f16.f16.f32 " \
        "{%0,%1,%2,%3}, {%4,%5,%6,%7}, {%8,%9}, {%0,%1,%2,%3};" \
        : "+f"((d)[0]), "+f"((d)[1]), "+f"((d)[2]), "+f"((d)[3]) \
        : "r"((a)[0]), "r"((a)[1]), "r"((a)[2]), "r"((a)[3]), "r"(b0), "r"(b1))

__device__ __forceinline__ void cp16(uint32_t dst, const void* src, int pred_sz) {
    asm volatile("cp.async.cg.shared.global [%0], [%1], 16, %2;"
                 :: "r"(dst), "l"(src), "r"(pred_sz));
}
#define CP_COMMIT() asm volatile("cp.async.commit_group;" ::: "memory")
#define CP_WAIT1()  asm volatile("cp.async.wait_group 1;" ::: "memory")
#define CP_WAIT0()  asm volatile("cp.async.wait_group 0;" ::: "memory")

// ---------------- init scratch ----------------
__global__ void init_scratch_kernel() {
    int i = blockIdx.x * blockDim.x + threadIdx.x;
    if (i < NUM_NODES * MAXP) g_tbl[i] = -1;
    if (i < N_O) g_cnt[i] = 0;
}

// ---------------- W -> fp16 ----------------
__global__ void w_h_kernel(const float* __restrict__ uw, const float* __restrict__ ow) {
    int i = blockIdx.x * blockDim.x + threadIdx.x;
    if (i >= CDIM * TXTD) return;
    int idx = i * 2;
    float a, b;
    if (idx < CDIM * TXTD) { a = uw[idx]; b = uw[idx + 1]; }
    else { a = ow[idx - CDIM * TXTD]; b = ow[idx - CDIM * TXTD + 1]; }
    __half2 h = __floats2half2_rn(a, b);
    *(uint32_t*)&g_w_h[idx] = *reinterpret_cast<uint32_t*>(&h);
}

// ---------------- edges: scatter + per-child sort ----------------
__global__ void edge_scatter_kernel(const int* __restrict__ edge_index) {
    int i = blockIdx.x * blockDim.x + threadIdx.x;
    if (i >= E_EDGES) return;
    int c = edge_index[i];
    int s = atomicAdd(&g_cnt[c], 1);
    if (s < 32) g_slot[c * 32 + s] = i;
}

__global__ void edge_sort_write_kernel(const int* __restrict__ edge_index) {
    int c = blockIdx.x * blockDim.x + threadIdx.x;
    if (c >= N_O) return;
    int n = g_cnt[c];
    if (n > 32) n = 32;
    int idx[32];
    for (int j = 0; j < n; j++) {
        int v = g_slot[c * 32 + j];
        int pos = j;
        while (pos > 0 && idx[pos - 1] > v) { idx[pos] = idx[pos - 1]; pos--; }
        idx[pos] = v;
    }
    int lim = n < MAXP ? n : MAXP;
    for (int r = 0; r < lim; r++)
        g_tbl[(N_U + c) * MAXP + r] = edge_index[E_EDGES + idx[r]];
}

// ---------------- f2p gather ----------------
__global__ void f2p_gather_kernel(float* __restrict__ out) {
    int i = blockIdx.x * blockDim.x + threadIdx.x;
    if (i >= X_ROWS * MAXP) return;
    int row = i >> 4;
    int s = i & (MAXP - 1);
    int node;
    if (row < NCOLS * N_U) node = row % N_U;
    else                   node = N_U + (row - NCOLS * N_U) % N_O;
    out[OFF_F2P + i] = (float)g_tbl[node * MAXP + s];
}

// ---------------- index arrays + num_nodes ----------------
__global__ void index_kernel(float* __restrict__ out) {
    int i = blockIdx.x * blockDim.x + threadIdx.x;
    if (i > 3 * X_ROWS) return;
    if (i == 3 * X_ROWS) { out[OFF_NN] = (float)NUM_NODES; return; }
    int r = i / X_ROWS;
    int j = i - r * X_ROWS;
    int node, colv, tabv;
    if (j < NCOLS * N_U) {
        node = j % N_U; colv = j / N_U; tabv = 0;
    } else {
        int jj = j - NCOLS * N_U;
        node = N_U + jj % N_O; colv = NCOLS + jj / N_O; tabv = 1;
    }
    if      (r == 0) out[OFF_NODE + j] = (float)node;
    else if (r == 1) out[OFF_COL  + j] = (float)colv;
    else             out[OFF_TAB  + j] = (float)tabv;
}

// ---------------- num + cat tokens ----------------
__global__ void tok_kernel(
    const float* __restrict__ unum, const int* __restrict__ ucat,
    const float* __restrict__ onum, const int* __restrict__ ocat,
    const float* __restrict__ u_nw, const float* __restrict__ u_nb,
    const float* __restrict__ u_ct, const float* __restrict__ u_col,
    const float* __restrict__ o_nw, const float* __restrict__ o_nb,
    const float* __restrict__ o_ct, const float* __restrict__ o_col,
    const float* __restrict__ temb, float* __restrict__ out)
{
    int rid = blockIdx.x * 4 + (threadIdx.x >> 6);
    int c4 = (threadIdx.x & 63) * 4;
    int k, n, row;
    const float *nw, *nb, *ct, *col, *te, *nump;
    const int* catp;
    if (rid < 6 * N_U) {
        k = rid / N_U; n = rid - k * N_U;
        row = k * N_U + n;
        nw = u_nw; nb = u_nb; ct = u_ct; col = u_col; te = temb;
        nump = unum; catp = ucat;
    } else {
        int b = rid - 6 * N_U;
        k = b / N_O; n = b - k * N_O;
        row = NCOLS * N_U + k * N_O + n;
        nw = o_nw; nb = o_nb; ct = o_ct; col = o_col; te = temb + CDIM;
        nump = onum; catp = ocat;
    }
    float4 v;
    if (k < 3) {
        float x = nump[n * 3 + k];
        float4 w = *(const float4*)&nw[k * CDIM + c4];
        float4 bb = *(const float4*)&nb[k * CDIM + c4];
        float z0 = x * w.x + bb.x, z1 = x * w.y + bb.y;
        float z2 = x * w.z + bb.z, z3 = x * w.w + bb.w;
        v.x = z0 / (1.0f + __expf(-z0));
        v.y = z1 / (1.0f + __expf(-z1));
        v.z = z2 / (1.0f + __expf(-z2));
        v.w = z3 / (1.0f + __expf(-z3));
    } else {
        int idx = catp[n * 3 + (k - 3)];
        v = *(const float4*)&ct[((k - 3) * VOCAB + idx) * CDIM + c4];
    }
    float4 cv = *(const float4*)&col[k * CDIM + c4];
    float4 tv = *(const float4*)&te[c4];
    v.x += cv.x + tv.x; v.y += cv.y + tv.y;
    v.z += cv.z + tv.z; v.w += cv.w + tv.w;
    *(float4*)&out[(size_t)row * CDIM + c4] = v;
}

// ---------------- persistent fp16 HMMA text GEMM (R11 exact + cvt-before-wait) ----------------
// 512 threads, CTA tile 128x256, warps 4(m) x 4(n), warp tile 32x64, grid 148.
// BK=64. A: fp32 reg-prefetch -> fp16 cvt (issued BEFORE the B wait, overlapping it).
// B: cp.async 3-stage, issued 2 chunks ahead.
#define U_TILES 157
#define O_TILES 79
#define NTILES  (U_TILES + O_TILES)
#define GEMM_GRID 148
#define BK      64
#define ROWB    144                      // 128B data + 16B pad (conflict-free LDSM)
#define TILEB_A (128 * ROWB)             // 18432
#define TILEB_B (256 * ROWB)             // 36864
#define SM_B0   (2 * TILEB_A)
#define SM_BIAS (2 * TILEB_A + 3 * TILEB_B)   // 147456
#define SM_TOT  (SM_BIAS + 1024)
#define KCH     (TXTD / BK)              // 24

__global__ void __launch_bounds__(512, 1) txt_gemm_mma(
    const float* __restrict__ uA, const float* __restrict__ oA,
    const float* __restrict__ u_tb, const float* __restrict__ u_col,
    const float* __restrict__ o_tb, const float* __restrict__ o_col,
    const float* __restrict__ temb, float* __restrict__ out)
{
    extern __shared__ char smem[];
    uint32_t sb = smem_u32(smem);

    int tid = threadIdx.x;
    int lane = tid & 31;
    int wid = tid >> 5;
    int warp_m = wid & 3;
    int warp_n = wid >> 2;

    // A load geometry: row = tid>>2 (0..127), 16 fp32 at (tid&3)*16
    int a_r   = tid >> 2;
    int a_c16 = (tid & 3) * 16;
    uint32_t a_sts = (uint32_t)(a_r * ROWB + a_c16 * 2);

    // B load geometry: 4 groups of 16B per thread (256 rows x 128B)
    int rB[4], csB[4];
    uint32_t dB[4];
    #pragma unroll
    for (int k = 0; k < 4; k++) {
        int g = tid + k * 512;
        rB[k] = g >> 3; csB[k] = g & 7;
        dB[k] = (uint32_t)(rB[k] * ROWB + csB[k] * 16);
    }

    // ldmatrix lane-invariant offsets
    uint32_t a_row = (uint32_t)(warp_m * 32 + (lane & 15));
    uint32_t a_ch  = (uint32_t)(lane >> 4);
    uint32_t b_row = (uint32_t)(warp_n * 64 + (lane & 7) + ((lane >> 4) << 3));
    uint32_t b_ch  = (uint32_t)((lane >> 3) & 1);

    float* s_bias = (float*)(smem + SM_BIAS);

    for (int tile = blockIdx.x; tile < NTILES; tile += GEMM_GRID) {
        const float* A;
        int M, m0, orow0, wrow0;
        const float *tb, *col, *te;
        if (tile < U_TILES) {
            A = uA; M = N_U; m0 = tile * 128; orow0 = 6 * N_U; wrow0 = 0;
            tb = u_tb; col = u_col; te = temb;
        } else {
            A = oA; M = N_O; m0 = (tile - U_TILES) * 128;
            orow0 = NCOLS * N_U + 6 * N_O; wrow0 = CDIM;
            tb = o_tb; col = o_col; te = temb + CDIM;
        }

        if (tid < 256) {
            s_bias[tid] = tb[tid] + col[6 * CDIM + tid] + te[tid];
        }

        float acc[2][8][4];
        #pragma unroll
        for (int mi = 0; mi < 2; mi++)
            #pragma unroll
            for (int nt = 0; nt < 8; nt++)
                #pragma unroll
                for (int q = 0; q < 4; q++) acc[mi][nt][q] = 0.0f;

        int a_gr = m0 + a_r;
        bool a_ok = (a_gr < M);
        const float* a_ptr = A + (size_t)(a_ok ? a_gr : 0) * TXTD + a_c16;

        size_t boff[4];
        #pragma unroll
        for (int k = 0; k < 4; k++)
            boff[k] = (size_t)(wrow0 + rB[k]) * TXTD + csB[k] * 8;

        auto load_B = [&](int s, int ch) {
            int k0 = ch * BK;
            uint32_t base = sb + SM_B0 + s * TILEB_B;
            #pragma unroll
            for (int k = 0; k < 4; k++)
                cp16(base + dB[k], &g_w_h[boff[k] + k0], 16);
            CP_COMMIT();
        };

        // prefetch A chunk 0 + B chunks 0,1
        float4 av0, av1, av2, av3;
        {
            const float4* p = (const float4*)a_ptr;
            if (a_ok) { av0 = p[0]; av1 = p[1]; av2 = p[2]; av3 = p[3]; }
            else { av0 = av1 = av2 = av3 = make_float4(0.f, 0.f, 0.f, 0.f); }
        }
        load_B(0, 0);
        load_B(1, 1);

        for (int ch = 0; ch < KCH; ch++) {
            int as_ = ch & 1;
            int bs  = ch % 3;

            // convert prefetched A -> fp16 SMEM (stage as_) FIRST — it doesn't
            // depend on B, so it overlaps any residual cp.async wait below.
            {
                uint32_t base = sb + as_ * TILEB_A;
                __half2 h0 = __floats2half2_rn(av0.x, av0.y);
                __half2 h1 = __floats2half2_rn(av0.z, av0.w);
                __half2 h2 = __floats2half2_rn(av1.x, av1.y);
                __half2 h3 = __floats2half2_rn(av1.z, av1.w);
                asm volatile("st.shared.v4.b32 [%0], {%1,%2,%3,%4};" ::
                    "r"(base + a_sts),
                    "r"(*reinterpret_cast<uint32_t*>(&h0)),
                    "r"(*reinterpret_cast<uint32_t*>(&h1)),
                    "r"(*reinterpret_cast<uint32_t*>(&h2)),
                    "r"(*reinterpret_cast<uint32_t*>(&h3)));
                __half2 h4 = __floats2half2_rn(av2.x, av2.y);
                __half2 h5 = __floats2half2_rn(av2.z, av2.w);
                __half2 h6 = __floats2half2_rn(av3.x, av3.y);
                __half2 h7 = __floats2half2_rn(av3.z, av3.w);
                asm volatile("st.shared.v4.b32 [%0], {%1,%2,%3,%4};" ::
                    "r"(base + a_sts + 16),
                    "r"(*reinterpret_cast<uint32_t*>(&h4)),
                    "r"(*reinterpret_cast<uint32_t*>(&h5)),
                    "r"(*reinterpret_cast<uint32_t*>(&h6)),
                    "r"(*reinterpret_cast<uint32_t*>(&h7)));
            }
            // prefetch A for next chunk
            if (ch + 1 < KCH) {
                const float4* p = (const float4*)(a_ptr + (ch + 1) * BK);
                if (a_ok) { av0 = p[0]; av1 = p[1]; av2 = p[2]; av3 = p[3]; }
            }

            if (ch + 1 < KCH) { CP_WAIT1(); }   // B(ch) landed, B(ch+1) may fly
            else              { CP_WAIT0(); }
            __syncthreads();   // A(as_) visible; all warps done MMAs of ch-1

            // stage (ch+2)%3 last read at chunk ch-1 -> safe to overwrite now
            if (ch + 2 < KCH) load_B((ch + 2) % 3, ch + 2);

            uint32_t sa  = sb + as_ * TILEB_A;
            uint32_t sbh = sb + SM_B0 + bs * TILEB_B;

            #pragma unroll
            for (int ks = 0; ks < 4; ks++) {
                uint32_t a_off = a_row * ROWB + (2 * ks + a_ch) * 16;
                uint32_t b_off = b_row * ROWB + (2 * ks + b_ch) * 16;

                uint32_t ah[2][4], bh[4][4];
                #pragma unroll
                for (int mi = 0; mi < 2; mi++)
                    LDSM_X4(ah[mi][0], ah[mi][1], ah[mi][2], ah[mi][3],
                            sa + a_off + mi * 16 * ROWB);
                #pragma unroll
                for (int np = 0; np < 4; np++)
                    LDSM_X4(bh[np][0], bh[np][1], bh[np][2], bh[np][3],
                            sbh + b_off + np * 16 * ROWB);
                #pragma unroll
                for (int mi = 0; mi < 2; mi++)
                    #pragma unroll
                    for (int np = 0; np < 4; np++) {
                        MMA16816H(acc[mi][2 * np],     ah[mi], bh[np][0], bh[np][1]);
                        MMA16816H(acc[mi][2 * np + 1], ah[mi], bh[np][2], bh[np][3]);
                    }
            }
        }

        // epilogue
        #pragma unroll
        for (int mi = 0; mi < 2; mi++) {
            #pragma unroll
            for (int rh = 0; rh < 2; rh++) {
                int row = m0 + warp_m * 32 + mi * 16 + (lane >> 2) + rh * 8;
                if (row >= M) continue;
                size_t rbase = (size_t)(orow0 + row) * CDIM;
                #pragma unroll
                for (int nt = 0; nt < 8; nt++) {
                    int cc = warp_n * 64 + nt * 8 + (lane & 3) * 2;
                    float2 o;
                    o.x = acc[mi][nt][rh * 2 + 0] + s_bias[cc];
                    o.y = acc[mi][nt][rh * 2 + 1] + s_bias[cc + 1];
                    *(float2*)&out[rbase + cc] = o;
                }
            }
        }
        __syncthreads();   // protect s_bias and smem stages before next tile
    }
}

// ---------------- launch ----------------
extern "C" void kernel_launch(void* const* d_in, const int* in_sizes, int n_in,
                              void* d_out, int out_size) {
    const float* users_num   = (const float*)d_in[0];
    const int*   users_cat   = (const int*)  d_in[1];
    const float* users_text  = (const float*)d_in[2];
    const float* orders_num  = (const float*)d_in[3];
    const int*   orders_cat  = (const int*)  d_in[4];
    const float* orders_text = (const float*)d_in[5];
    const int*   edge_index  = (const int*)  d_in[6];
    const float* table_emb   = (const float*)d_in[7];
    const float* u_num_w     = (const float*)d_in[8];
    const float* u_num_b     = (const float*)d_in[9];
    const float* u_cat_tab   = (const float*)d_in[10];
    const float* u_txt_w     = (const float*)d_in[11];
    const float* u_txt_b     = (const float*)d_in[12];
    const float* u_col       = (const float*)d_in[13];
    const float* o_num_w     = (const float*)d_in[14];
    const float* o_num_b     = (const float*)d_in[15];
    const float* o_cat_tab   = (const float*)d_in[16];
    const float* o_txt_w     = (const float*)d_in[17];
    const float* o_txt_b     = (const float*)d_in[18];
    const float* o_col       = (const float*)d_in[19];

    float* out = (float*)d_out;

    // one-time host-side setup (no device allocations)
    static cudaStream_t s2 = nullptr;
    static cudaEvent_t evFork = nullptr, evJoin = nullptr;
    static bool setup_done = false;
    if (!setup_done) {
        cudaFuncSetAttribute(txt_gemm_mma, cudaFuncAttributeMaxDynamicSharedMemorySize, SM_TOT);
        if (cudaStreamCreateWithFlags(&s2, cudaStreamNonBlocking) != cudaSuccess) s2 = nullptr;
        if (s2) {
            cudaEventCreateWithFlags(&evFork, cudaEventDisableTiming);
            cudaEventCreateWithFlags(&evJoin, cudaEventDisableTiming);
        }
        setup_done = true;
    }

    cudaStream_t side = s2 ? s2 : (cudaStream_t)0;
    if (s2) {
        cudaEventRecord(evFork, 0);
        cudaStreamWaitEvent(s2, evFork, 0);
    }

    // ---- main branch FIRST (captured/enqueued ahead of side work so the GEMM
    // grabs the SMs; the side kernels backfill the GEMM's single-tile tail) ----
    w_h_kernel<<<(CDIM * TXTD + 255) / 256, 256>>>(u_txt_w, o_txt_w);
    txt_gemm_mma<<<GEMM_GRID, 512, SM_TOT>>>(
        users_text, orders_text,
        u_txt_b, u_col, o_txt_b, o_col, table_emb, out);

    // ---- side branch: edge table, gathers, indices, tokens ----
    init_scratch_kernel<<<(NUM_NODES * MAXP + 255) / 256, 256, 0, side>>>();
    edge_scatter_kernel<<<(E_EDGES + 255) / 256, 256, 0, side>>>(edge_index);
    edge_sort_write_kernel<<<(N_O + 255) / 256, 256, 0, side>>>(edge_index);
    f2p_gather_kernel<<<(X_ROWS * MAXP + 255) / 256, 256, 0, side>>>(out);
    index_kernel<<<(3 * X_ROWS + 1 + 255) / 256, 256, 0, side>>>(out);
    tok_kernel<<<(6 * N_U + 6 * N_O) / 4, 256, 0, side>>>(
        users_num, users_cat, orders_num, orders_cat,
        u_num_w, u_num_b, u_cat_tab, u_col,
        o_num_w, o_num_b, o_cat_tab, o_col,
        table_emb, out);
    if (s2) {
        cudaEventRecord(evJoin, s2);
        cudaStreamWaitEvent(0, evJoin, 0);
    }
}

// round 17
// speedup vs baseline: 1.3506x; 1.0002x over previous
#include <cuda_runtime.h>
#include <cuda_fp16.h>
#include <cstdint>

// ---------------- problem constants ----------------
#define N_U      20000
#define N_O      10000
#define N_TOT    30000
#define CDIM     256
#define TXTD     1536
#define NCOLS    7
#define E_EDGES  10000
#define MAXP     16
#define NUM_NODES 30000
#define VOCAB    101

#define X_ROWS   210000
#define OFF_NODE 53760000
#define OFF_COL  53970000
#define OFF_TAB  54180000
#define OFF_F2P  54390000
#define OFF_NN   57750000

// ---------------- device scratch ----------------
__device__ int g_tbl[NUM_NODES * MAXP];
__device__ int g_cnt[N_O];
__device__ int g_slot[N_O * 32];
__device__ __half g_w_h[2 * CDIM * TXTD];   // W rounded to fp16

// ---------------- helpers ----------------
__device__ __forceinline__ uint32_t smem_u32(const void* p) {
    uint32_t a;
    asm("{ .reg .u64 t; cvta.to.shared.u64 t, %1; cvt.u32.u64 %0, t; }" : "=r"(a) : "l"(p));
    return a;
}

#define LDSM_X4(r0, r1, r2, r3, addr) \
    asm volatile("ldmatrix.sync.aligned.m8n8.x4.shared.b16 {%0,%1,%2,%3}, [%4];" \
        : "=r"(r0), "=r"(r1), "=r"(r2), "=r"(r3) : "r"(addr))

#define MMA16816H(d, a, b0, b1) \
    asm volatile("mma.sync.aligned.m16n8k16.row.col.f32.f16.f16.f32 " \
        "{%0,%1,%2,%3}, {%4,%5,%6,%7}, {%8,%9}, {%0,%1,%2,%3};" \
        : "+f"((d)[0]), "+f"((d)[1]), "+f"((d)[2]), "+f"((d)[3]) \
        : "r"((a)[0]), "r"((a)[1]), "r"((a)[2]), "r"((a)[3]), "r"(b0), "r"(b1))

__device__ __forceinline__ void cp16(uint32_t dst, const void* src, int pred_sz) {
    asm volatile("cp.async.cg.shared.global [%0], [%1], 16, %2;"
                 :: "r"(dst), "l"(src), "r"(pred_sz));
}
#define CP_COMMIT() asm volatile("cp.async.commit_group;" ::: "memory")
#define CP_WAIT2()  asm volatile("cp.async.wait_group 2;" ::: "memory")
#define CP_WAIT0()  asm volatile("cp.async.wait_group 0;" ::: "memory")

// ---------------- init scratch ----------------
__global__ void init_scratch_kernel() {
    int i = blockIdx.x * blockDim.x + threadIdx.x;
    if (i < NUM_NODES * MAXP) g_tbl[i] = -1;
    if (i < N_O) g_cnt[i] = 0;
}

// ---------------- W -> fp16 ----------------
__global__ void w_h_kernel(const float* __restrict__ uw, const float* __restrict__ ow) {
    int i = blockIdx.x * blockDim.x + threadIdx.x;
    if (i >= CDIM * TXTD) return;
    int idx = i * 2;
    float a, b;
    if (idx < CDIM * TXTD) { a = uw[idx]; b = uw[idx + 1]; }
    else { a = ow[idx - CDIM * TXTD]; b = ow[idx - CDIM * TXTD + 1]; }
    __half2 h = __floats2half2_rn(a, b);
    *(uint32_t*)&g_w_h[idx] = *reinterpret_cast<uint32_t*>(&h);
}

// ---------------- edges: scatter + per-child sort ----------------
__global__ void edge_scatter_kernel(const int* __restrict__ edge_index) {
    int i = blockIdx.x * blockDim.x + threadIdx.x;
    if (i >= E_EDGES) return;
    int c = edge_index[i];
    int s = atomicAdd(&g_cnt[c], 1);
    if (s < 32) g_slot[c * 32 + s] = i;
}

__global__ void edge_sort_write_kernel(const int* __restrict__ edge_index) {
    int c = blockIdx.x * blockDim.x + threadIdx.x;
    if (c >= N_O) return;
    int n = g_cnt[c];
    if (n > 32) n = 32;
    int idx[32];
    for (int j = 0; j < n; j++) {
        int v = g_slot[c * 32 + j];
        int pos = j;
        while (pos > 0 && idx[pos - 1] > v) { idx[pos] = idx[pos - 1]; pos--; }
        idx[pos] = v;
    }
    int lim = n < MAXP ? n : MAXP;
    for (int r = 0; r < lim; r++)
        g_tbl[(N_U + c) * MAXP + r] = edge_index[E_EDGES + idx[r]];
}

// ---------------- f2p gather ----------------
__global__ void f2p_gather_kernel(float* __restrict__ out) {
    int i = blockIdx.x * blockDim.x + threadIdx.x;
    if (i >= X_ROWS * MAXP) return;
    int row = i >> 4;
    int s = i & (MAXP - 1);
    int node;
    if (row < NCOLS * N_U) node = row % N_U;
    else                   node = N_U + (row - NCOLS * N_U) % N_O;
    out[OFF_F2P + i] = (float)g_tbl[node * MAXP + s];
}

// ---------------- index arrays + num_nodes ----------------
__global__ void index_kernel(float* __restrict__ out) {
    int i = blockIdx.x * blockDim.x + threadIdx.x;
    if (i > 3 * X_ROWS) return;
    if (i == 3 * X_ROWS) { out[OFF_NN] = (float)NUM_NODES; return; }
    int r = i / X_ROWS;
    int j = i - r * X_ROWS;
    int node, colv, tabv;
    if (j < NCOLS * N_U) {
        node = j % N_U; colv = j / N_U; tabv = 0;
    } else {
        int jj = j - NCOLS * N_U;
        node = N_U + jj % N_O; colv = NCOLS + jj / N_O; tabv = 1;
    }
    if      (r == 0) out[OFF_NODE + j] = (float)node;
    else if (r == 1) out[OFF_COL  + j] = (float)colv;
    else             out[OFF_TAB  + j] = (float)tabv;
}

// ---------------- num + cat tokens ----------------
__global__ void tok_kernel(
    const float* __restrict__ unum, const int* __restrict__ ucat,
    const float* __restrict__ onum, const int* __restrict__ ocat,
    const float* __restrict__ u_nw, const float* __restrict__ u_nb,
    const float* __restrict__ u_ct, const float* __restrict__ u_col,
    const float* __restrict__ o_nw, const float* __restrict__ o_nb,
    const float* __restrict__ o_ct, const float* __restrict__ o_col,
    const float* __restrict__ temb, float* __restrict__ out)
{
    int rid = blockIdx.x * 4 + (threadIdx.x >> 6);
    int c4 = (threadIdx.x & 63) * 4;
    int k, n, row;
    const float *nw, *nb, *ct, *col, *te, *nump;
    const int* catp;
    if (rid < 6 * N_U) {
        k = rid / N_U; n = rid - k * N_U;
        row = k * N_U + n;
        nw = u_nw; nb = u_nb; ct = u_ct; col = u_col; te = temb;
        nump = unum; catp = ucat;
    } else {
        int b = rid - 6 * N_U;
        k = b / N_O; n = b - k * N_O;
        row = NCOLS * N_U + k * N_O + n;
        nw = o_nw; nb = o_nb; ct = o_ct; col = o_col; te = temb + CDIM;
        nump = onum; catp = ocat;
    }
    float4 v;
    if (k < 3) {
        float x = nump[n * 3 + k];
        float4 w = *(const float4*)&nw[k * CDIM + c4];
        float4 bb = *(const float4*)&nb[k * CDIM + c4];
        float z0 = x * w.x + bb.x, z1 = x * w.y + bb.y;
        float z2 = x * w.z + bb.z, z3 = x * w.w + bb.w;
        v.x = z0 / (1.0f + __expf(-z0));
        v.y = z1 / (1.0f + __expf(-z1));
        v.z = z2 / (1.0f + __expf(-z2));
        v.w = z3 / (1.0f + __expf(-z3));
    } else {
        int idx = catp[n * 3 + (k - 3)];
        v = *(const float4*)&ct[((k - 3) * VOCAB + idx) * CDIM + c4];
    }
    float4 cv = *(const float4*)&col[k * CDIM + c4];
    float4 tv = *(const float4*)&te[c4];
    v.x += cv.x + tv.x; v.y += cv.y + tv.y;
    v.z += cv.z + tv.z; v.w += cv.w + tv.w;
    *(float4*)&out[(size_t)row * CDIM + c4] = v;
}

// ---------------- persistent fp16 HMMA text GEMM ----------------
// R16 champion + (a) bias hoisted out of tile loop (both tables precomputed,
// end-of-tile barrier dropped), (b) 4-stage B pipeline with wait_group 2.
// 512 threads, CTA tile 128x256, warps 4(m) x 4(n), warp tile 32x64, grid 148.
#define U_TILES 157
#define O_TILES 79
#define NTILES  (U_TILES + O_TILES)
#define GEMM_GRID 148
#define BK      64
#define ROWB    144                      // 128B data + 16B pad (conflict-free LDSM)
#define TILEB_A (128 * ROWB)             // 18432
#define TILEB_B (256 * ROWB)             // 36864
#define NBSTG   4
#define SM_B0   (2 * TILEB_A)            // 36864
#define SM_BIAS (SM_B0 + NBSTG * TILEB_B)   // 184320
#define SM_TOT  (SM_BIAS + 2048)         // 186368 < 227KB
#define KCH     (TXTD / BK)              // 24

__global__ void __launch_bounds__(512, 1) txt_gemm_mma(
    const float* __restrict__ uA, const float* __restrict__ oA,
    const float* __restrict__ u_tb, const float* __restrict__ u_col,
    const float* __restrict__ o_tb, const float* __restrict__ o_col,
    const float* __restrict__ temb, float* __restrict__ out)
{
    extern __shared__ char smem[];
    uint32_t sb = smem_u32(smem);

    int tid = threadIdx.x;
    int lane = tid & 31;
    int wid = tid >> 5;
    int warp_m = wid & 3;
    int warp_n = wid >> 2;

    // A load geometry: row = tid>>2 (0..127), 16 fp32 at (tid&3)*16
    int a_r   = tid >> 2;
    int a_c16 = (tid & 3) * 16;
    uint32_t a_sts = (uint32_t)(a_r * ROWB + a_c16 * 2);

    // B load geometry: 4 groups of 16B per thread (256 rows x 128B)
    int rB[4], csB[4];
    uint32_t dB[4];
    #pragma unroll
    for (int k = 0; k < 4; k++) {
        int g = tid + k * 512;
        rB[k] = g >> 3; csB[k] = g & 7;
        dB[k] = (uint32_t)(rB[k] * ROWB + csB[k] * 16);
    }

    // ldmatrix lane-invariant offsets
    uint32_t a_row = (uint32_t)(warp_m * 32 + (lane & 15));
    uint32_t a_ch  = (uint32_t)(lane >> 4);
    uint32_t b_row = (uint32_t)(warp_n * 64 + (lane & 7) + ((lane >> 4) << 3));
    uint32_t b_ch  = (uint32_t)((lane >> 3) & 1);

    // bias precompute: [0..255] users, [256..511] orders — once per kernel
    float* s_bias = (float*)(smem + SM_BIAS);
    if (tid < 256) {
        s_bias[tid]       = u_tb[tid] + u_col[6 * CDIM + tid] + temb[tid];
        s_bias[256 + tid] = o_tb[tid] + o_col[6 * CDIM + tid] + temb[CDIM + tid];
    }
    __syncthreads();

    for (int tile = blockIdx.x; tile < NTILES; tile += GEMM_GRID) {
        const float* A;
        int M, m0, orow0, wrow0, bias0;
        if (tile < U_TILES) {
            A = uA; M = N_U; m0 = tile * 128; orow0 = 6 * N_U; wrow0 = 0; bias0 = 0;
        } else {
            A = oA; M = N_O; m0 = (tile - U_TILES) * 128;
            orow0 = NCOLS * N_U + 6 * N_O; wrow0 = CDIM; bias0 = 256;
        }

        float acc[2][8][4];
        #pragma unroll
        for (int mi = 0; mi < 2; mi++)
            #pragma unroll
            for (int nt = 0; nt < 8; nt++)
                #pragma unroll
                for (int q = 0; q < 4; q++) acc[mi][nt][q] = 0.0f;

        int a_gr = m0 + a_r;
        bool a_ok = (a_gr < M);
        const float* a_ptr = A + (size_t)(a_ok ? a_gr : 0) * TXTD + a_c16;

        size_t boff[4];
        #pragma unroll
        for (int k = 0; k < 4; k++)
            boff[k] = (size_t)(wrow0 + rB[k]) * TXTD + csB[k] * 8;

        auto load_B = [&](int s, int ch) {
            int k0 = ch * BK;
            uint32_t base = sb + SM_B0 + s * TILEB_B;
            #pragma unroll
            for (int k = 0; k < 4; k++)
                cp16(base + dB[k], &g_w_h[boff[k] + k0], 16);
            CP_COMMIT();
        };

        // prefetch A chunk 0 + B chunks 0..2
        float4 av0, av1, av2, av3;
        {
            const float4* p = (const float4*)a_ptr;
            if (a_ok) { av0 = p[0]; av1 = p[1]; av2 = p[2]; av3 = p[3]; }
            else { av0 = av1 = av2 = av3 = make_float4(0.f, 0.f, 0.f, 0.f); }
        }
        load_B(0, 0);
        load_B(1, 1);
        load_B(2, 2);

        for (int ch = 0; ch < KCH; ch++) {
            int as_ = ch & 1;
            int bs  = ch & 3;

            // convert prefetched A -> fp16 SMEM (stage as_) BEFORE the B wait
            {
                uint32_t base = sb + as_ * TILEB_A;
                __half2 h0 = __floats2half2_rn(av0.x, av0.y);
                __half2 h1 = __floats2half2_rn(av0.z, av0.w);
                __half2 h2 = __floats2half2_rn(av1.x, av1.y);
                __half2 h3 = __floats2half2_rn(av1.z, av1.w);
                asm volatile("st.shared.v4.b32 [%0], {%1,%2,%3,%4};" ::
                    "r"(base + a_sts),
                    "r"(*reinterpret_cast<uint32_t*>(&h0)),
                    "r"(*reinterpret_cast<uint32_t*>(&h1)),
                    "r"(*reinterpret_cast<uint32_t*>(&h2)),
                    "r"(*reinterpret_cast<uint32_t*>(&h3)));
                __half2 h4 = __floats2half2_rn(av2.x, av2.y);
                __half2 h5 = __floats2half2_rn(av2.z, av2.w);
                __half2 h6 = __floats2half2_rn(av3.x, av3.y);
                __half2 h7 = __floats2half2_rn(av3.z, av3.w);
                asm volatile("st.shared.v4.b32 [%0], {%1,%2,%3,%4};" ::
                    "r"(base + a_sts + 16),
                    "r"(*reinterpret_cast<uint32_t*>(&h4)),
                    "r"(*reinterpret_cast<uint32_t*>(&h5)),
                    "r"(*reinterpret_cast<uint32_t*>(&h6)),
                    "r"(*reinterpret_cast<uint32_t*>(&h7)));
            }
            // prefetch A for next chunk
            if (ch + 1 < KCH) {
                const float4* p = (const float4*)(a_ptr + (ch + 1) * BK);
                if (a_ok) { av0 = p[0]; av1 = p[1]; av2 = p[2]; av3 = p[3]; }
            }

            if (ch + 3 < KCH)      { CP_WAIT2(); }   // B(ch) landed; B(ch+1..2) may fly
            else if (ch + 1 < KCH) { CP_WAIT2(); }   // tail: <=2 groups outstanding
            else                   { CP_WAIT0(); }
            __syncthreads();   // A(as_) visible; all warps done MMAs of ch-1

            // B stage (ch+3)%4 last read at chunk ch-1 -> safe to overwrite now
            if (ch + 3 < KCH) load_B((ch + 3) & 3, ch + 3);

            uint32_t sa  = sb + as_ * TILEB_A;
            uint32_t sbh = sb + SM_B0 + bs * TILEB_B;

            #pragma unroll
            for (int ks = 0; ks < 4; ks++) {
                uint32_t a_off = a_row * ROWB + (2 * ks + a_ch) * 16;
                uint32_t b_off = b_row * ROWB + (2 * ks + b_ch) * 16;

                uint32_t ah[2][4], bh[4][4];
                #pragma unroll
                for (int mi = 0; mi < 2; mi++)
                    LDSM_X4(ah[mi][0], ah[mi][1], ah[mi][2], ah[mi][3],
                            sa + a_off + mi * 16 * ROWB);
                #pragma unroll
                for (int np = 0; np < 4; np++)
                    LDSM_X4(bh[np][0], bh[np][1], bh[np][2], bh[np][3],
                            sbh + b_off + np * 16 * ROWB);
                #pragma unroll
                for (int mi = 0; mi < 2; mi++)
                    #pragma unroll
                    for (int np = 0; np < 4; np++) {
                        MMA16816H(acc[mi][2 * np],     ah[mi], bh[np][0], bh[np][1]);
                        MMA16816H(acc[mi][2 * np + 1], ah[mi], bh[np][2], bh[np][3]);
                    }
            }
        }

        // epilogue (s_bias constant across tiles; no trailing barrier needed —
        // next tile's load_B(0..2) targets stages whose last readers are behind
        // barrier(KCH-1), and lagging warps here touch only regs + s_bias)
        #pragma unroll
        for (int mi = 0; mi < 2; mi++) {
            #pragma unroll
            for (int rh = 0; rh < 2; rh++) {
                int row = m0 + warp_m * 32 + mi * 16 + (lane >> 2) + rh * 8;
                if (row >= M) continue;
                size_t rbase = (size_t)(orow0 + row) * CDIM;
                #pragma unroll
                for (int nt = 0; nt < 8; nt++) {
                    int cc = warp_n * 64 + nt * 8 + (lane & 3) * 2;
                    float2 o;
                    o.x = acc[mi][nt][rh * 2 + 0] + s_bias[bias0 + cc];
                    o.y = acc[mi][nt][rh * 2 + 1] + s_bias[bias0 + cc + 1];
                    *(float2*)&out[rbase + cc] = o;
                }
            }
        }
    }
}

// ---------------- launch ----------------
extern "C" void kernel_launch(void* const* d_in, const int* in_sizes, int n_in,
                              void* d_out, int out_size) {
    const float* users_num   = (const float*)d_in[0];
    const int*   users_cat   = (const int*)  d_in[1];
    const float* users_text  = (const float*)d_in[2];
    const float* orders_num  = (const float*)d_in[3];
    const int*   orders_cat  = (const int*)  d_in[4];
    const float* orders_text = (const float*)d_in[5];
    const int*   edge_index  = (const int*)  d_in[6];
    const float* table_emb   = (const float*)d_in[7];
    const float* u_num_w     = (const float*)d_in[8];
    const float* u_num_b     = (const float*)d_in[9];
    const float* u_cat_tab   = (const float*)d_in[10];
    const float* u_txt_w     = (const float*)d_in[11];
    const float* u_txt_b     = (const float*)d_in[12];
    const float* u_col       = (const float*)d_in[13];
    const float* o_num_w     = (const float*)d_in[14];
    const float* o_num_b     = (const float*)d_in[15];
    const float* o_cat_tab   = (const float*)d_in[16];
    const float* o_txt_w     = (const float*)d_in[17];
    const float* o_txt_b     = (const float*)d_in[18];
    const float* o_col       = (const float*)d_in[19];

    float* out = (float*)d_out;

    // one-time host-side setup (no device allocations)
    static cudaStream_t s2 = nullptr;
    static cudaEvent_t evFork = nullptr, evJoin = nullptr;
    static bool setup_done = false;
    if (!setup_done) {
        cudaFuncSetAttribute(txt_gemm_mma, cudaFuncAttributeMaxDynamicSharedMemorySize, SM_TOT);
        if (cudaStreamCreateWithFlags(&s2, cudaStreamNonBlocking) != cudaSuccess) s2 = nullptr;
        if (s2) {
            cudaEventCreateWithFlags(&evFork, cudaEventDisableTiming);
            cudaEventCreateWithFlags(&evJoin, cudaEventDisableTiming);
        }
        setup_done = true;
    }

    cudaStream_t side = s2 ? s2 : (cudaStream_t)0;
    if (s2) {
        cudaEventRecord(evFork, 0);
        cudaStreamWaitEvent(s2, evFork, 0);
    }

    // ---- main branch FIRST (GEMM grabs SMs; side kernels backfill the tail) ----
    w_h_kernel<<<(CDIM * TXTD + 255) / 256, 256>>>(u_txt_w, o_txt_w);
    txt_gemm_mma<<<GEMM_GRID, 512, SM_TOT>>>(
        users_text, orders_text,
        u_txt_b, u_col, o_txt_b, o_col, table_emb, out);

    // ---- side branch: edge table, gathers, indices, tokens ----
    init_scratch_kernel<<<(NUM_NODES * MAXP + 255) / 256, 256, 0, side>>>();
    edge_scatter_kernel<<<(E_EDGES + 255) / 256, 256, 0, side>>>(edge_index);
    edge_sort_write_kernel<<<(N_O + 255) / 256, 256, 0, side>>>(edge_index);
    f2p_gather_kernel<<<(X_ROWS * MAXP + 255) / 256, 256, 0, side>>>(out);
    index_kernel<<<(3 * X_ROWS + 1 + 255) / 256, 256, 0, side>>>(out);
    tok_kernel<<<(6 * N_U + 6 * N_O) / 4, 256, 0, side>>>(
        users_num, users_cat, orders_num, orders_cat,
        u_num_w, u_num_b, u_cat_tab, u_col,
        o_num_w, o_num_b, o_cat_tab, o_col,
        table_emb, out);
    if (s2) {
        cudaEventRecord(evJoin, s2);
        cudaStreamWaitEvent(0, evJoin, 0);
    }
}